// round 1
// baseline (speedup 1.0000x reference)
#include <cuda_runtime.h>
#include <cuda_bf16.h>
#include <math.h>

#define BB 2
#define SS 1024
#define DD 768
#define HH 12
#define HDD 64
#define LL 12
#define VV 50257
#define FF 3072
#define MM (BB*SS)   // 2048

// ---------------- scratch (allocation-free) ----------------
__device__ float g_x[MM*DD];
__device__ float g_h[MM*DD];
__device__ float g_q[MM*DD];
__device__ float g_k[MM*DD];
__device__ float g_v[MM*DD];
__device__ float g_attn[MM*DD];
__device__ float g_ff[MM*FF];
__device__ float g_scores[(size_t)BB*HH*SS*SS];
__device__ int   g_pos[BB*SS];

// ---------------- position ids (cumsum of mask) ----------------
__global__ void posids_kernel(const float* __restrict__ amask, int* __restrict__ pos) {
    int b = blockIdx.x;
    if (threadIdx.x == 0) {
        float c = 0.f;
        for (int s = 0; s < SS; s++) {
            float m = amask[b*SS + s];
            c += m;
            float pi = c - 1.f;
            pos[b*SS + s] = (m == 0.f) ? 0 : (int)pi;
        }
    }
}

// ---------------- embedding ----------------
__global__ void embed_kernel(const int* __restrict__ ids, const int* __restrict__ pos,
                             const float* __restrict__ tok, const float* __restrict__ pemb,
                             float* __restrict__ x) {
    int row = blockIdx.x;                 // 0..M-1
    int id = ids[row];
    int p  = pos[row];
    int tid = threadIdx.x;
    #pragma unroll
    for (int t = 0; t < 3; t++) {
        int d = tid + t*256;
        x[(size_t)row*DD + d] = tok[(size_t)id*DD + d] + pemb[(size_t)p*DD + d];
    }
}

// ---------------- layernorm (one block per row) ----------------
__global__ void layernorm_kernel(const float* __restrict__ x, const float* __restrict__ g,
                                 const float* __restrict__ b, float* __restrict__ y) {
    __shared__ float red[256];
    int row = blockIdx.x;
    int tid = threadIdx.x;
    const float* xr = x + (size_t)row*DD;
    float v0 = xr[tid], v1 = xr[tid+256], v2 = xr[tid+512];
    red[tid] = v0 + v1 + v2;
    __syncthreads();
    for (int s = 128; s > 0; s >>= 1) { if (tid < s) red[tid] += red[tid+s]; __syncthreads(); }
    float mu = red[0] * (1.f/DD);
    __syncthreads();
    float d0 = v0-mu, d1 = v1-mu, d2 = v2-mu;
    red[tid] = d0*d0 + d1*d1 + d2*d2;
    __syncthreads();
    for (int s = 128; s > 0; s >>= 1) { if (tid < s) red[tid] += red[tid+s]; __syncthreads(); }
    float rstd = rsqrtf(red[0] * (1.f/DD) + 1e-5f);
    float* yr = y + (size_t)row*DD;
    yr[tid]     = d0*rstd*g[tid]     + b[tid];
    yr[tid+256] = d1*rstd*g[tid+256] + b[tid+256];
    yr[tid+512] = d2*rstd*g[tid+512] + b[tid+512];
}

__device__ __forceinline__ float gelu_exact(float v) {
    return 0.5f * v * (1.0f + erff(v * 0.70710678118654752f));
}

// ---------------- SGEMM: C = A(MxK) @ B + bias [+gelu] [+res] ----------------
// TRANSB=0: B stored (K,N) row-major.  TRANSB=1: B stored (N,K) row-major.
template<int TRANSB>
__global__ void sgemm_kernel(const float* __restrict__ A, const float* __restrict__ Bw,
                             const float* __restrict__ bias, const float* __restrict__ res,
                             float* __restrict__ C, int M, int N, int K, int act) {
    const int BM=128, BN=128, BK=8, TM=8, TN=8;
    __shared__ float As[BK][BM];
    __shared__ float Bs[BK][BN];
    int tid = threadIdx.x;
    int tx = tid & 15, ty = tid >> 4;
    int m0 = blockIdx.y * BM, n0 = blockIdx.x * BN;
    float acc[TM][TN];
    #pragma unroll
    for (int i = 0; i < TM; i++)
        #pragma unroll
        for (int j = 0; j < TN; j++) acc[i][j] = 0.f;

    int aRow = tid >> 1;
    int aK   = (tid & 1) * 4;
    float4 z4 = make_float4(0.f,0.f,0.f,0.f);

    for (int k0 = 0; k0 < K; k0 += BK) {
        float4 av = *reinterpret_cast<const float4*>(A + (size_t)(m0+aRow)*K + k0 + aK);
        As[aK+0][aRow]=av.x; As[aK+1][aRow]=av.y; As[aK+2][aRow]=av.z; As[aK+3][aRow]=av.w;
        if (TRANSB) {
            int nL = tid >> 1, kk = (tid & 1) * 4;
            float4 bv = (n0+nL < N)
                ? *reinterpret_cast<const float4*>(Bw + (size_t)(n0+nL)*K + k0 + kk) : z4;
            Bs[kk+0][nL]=bv.x; Bs[kk+1][nL]=bv.y; Bs[kk+2][nL]=bv.z; Bs[kk+3][nL]=bv.w;
        } else {
            int bRow = tid >> 5, bc = (tid & 31) * 4;
            float4 bv = *reinterpret_cast<const float4*>(Bw + (size_t)(k0+bRow)*N + n0 + bc);
            *reinterpret_cast<float4*>(&Bs[bRow][bc]) = bv;
        }
        __syncthreads();
        #pragma unroll
        for (int kk = 0; kk < BK; kk++) {
            float4 a0 = *reinterpret_cast<const float4*>(&As[kk][ty*TM]);
            float4 a1 = *reinterpret_cast<const float4*>(&As[kk][ty*TM+4]);
            float4 b0 = *reinterpret_cast<const float4*>(&Bs[kk][tx*TN]);
            float4 b1 = *reinterpret_cast<const float4*>(&Bs[kk][tx*TN+4]);
            float ra[TM] = {a0.x,a0.y,a0.z,a0.w,a1.x,a1.y,a1.z,a1.w};
            float rb[TN] = {b0.x,b0.y,b0.z,b0.w,b1.x,b1.y,b1.z,b1.w};
            #pragma unroll
            for (int i = 0; i < TM; i++)
                #pragma unroll
                for (int j = 0; j < TN; j++) acc[i][j] = fmaf(ra[i], rb[j], acc[i][j]);
        }
        __syncthreads();
    }

    #pragma unroll
    for (int i = 0; i < TM; i++) {
        int m = m0 + ty*TM + i;
        #pragma unroll
        for (int j = 0; j < TN; j++) {
            int n = n0 + tx*TN + j;
            if (n < N) {
                float v = acc[i][j];
                if (bias) v += bias[n];
                if (act == 1) v = gelu_exact(v);
                if (res) v += res[(size_t)m*N + n];
                C[(size_t)m*N + n] = v;
            }
        }
    }
}

// ---------------- attention scores: QK^T * scale + causal/key mask --------
__global__ void attn_scores_kernel(const float* __restrict__ q, const float* __restrict__ k,
                                   const float* __restrict__ amask, float* __restrict__ sc) {
    int bh = blockIdx.z;
    int b = bh / HH, h = bh % HH;
    int q0 = blockIdx.y * 64, k0 = blockIdx.x * 64;
    int tid = threadIdx.x;
    int tx = tid & 15, ty = tid >> 4;

    if (k0 > q0 + 63) {  // whole tile above diagonal
        #pragma unroll
        for (int i = 0; i < 4; i++)
            #pragma unroll
            for (int j = 0; j < 4; j++)
                sc[((size_t)bh*SS + q0 + ty*4 + i)*SS + k0 + tx*4 + j] = -1e30f;
        return;
    }

    __shared__ float Qs[64][65];
    __shared__ float Ks[64][65];
    #pragma unroll
    for (int t = 0; t < 16; t++) {
        int idx = tid + t*256;
        int r = idx >> 6, d = idx & 63;
        Qs[d][r] = q[(size_t)(b*SS + q0 + r)*DD + h*HDD + d];
        Ks[d][r] = k[(size_t)(b*SS + k0 + r)*DD + h*HDD + d];
    }
    __syncthreads();

    float acc[4][4];
    #pragma unroll
    for (int i=0;i<4;i++)
        #pragma unroll
        for (int j=0;j<4;j++) acc[i][j]=0.f;
    #pragma unroll 8
    for (int d = 0; d < 64; d++) {
        float ra[4], rb[4];
        #pragma unroll
        for (int i = 0; i < 4; i++) ra[i] = Qs[d][ty*4+i];
        #pragma unroll
        for (int j = 0; j < 4; j++) rb[j] = Ks[d][tx*4+j];
        #pragma unroll
        for (int i = 0; i < 4; i++)
            #pragma unroll
            for (int j = 0; j < 4; j++) acc[i][j] = fmaf(ra[i], rb[j], acc[i][j]);
    }
    const float scale = 0.125f;  // 1/sqrt(64)
    #pragma unroll
    for (int i = 0; i < 4; i++) {
        int qr = q0 + ty*4 + i;
        #pragma unroll
        for (int j = 0; j < 4; j++) {
            int kc = k0 + tx*4 + j;
            bool ok = (kc <= qr) && (amask[b*SS + kc] != 0.f);
            sc[((size_t)bh*SS + qr)*SS + kc] = ok ? acc[i][j]*scale : -1e30f;
        }
    }
}

// ---------------- rowwise softmax ----------------
__global__ void softmax_kernel(float* __restrict__ sc) {
    __shared__ float red[256];
    size_t row = blockIdx.x;
    float* p = sc + row*SS;
    int tid = threadIdx.x;
    float4 v = *reinterpret_cast<float4*>(p + tid*4);
    float mx = fmaxf(fmaxf(v.x, v.y), fmaxf(v.z, v.w));
    red[tid] = mx; __syncthreads();
    for (int s = 128; s > 0; s >>= 1) { if (tid < s) red[tid] = fmaxf(red[tid], red[tid+s]); __syncthreads(); }
    mx = red[0]; __syncthreads();
    v.x = __expf(v.x - mx); v.y = __expf(v.y - mx); v.z = __expf(v.z - mx); v.w = __expf(v.w - mx);
    red[tid] = v.x + v.y + v.z + v.w; __syncthreads();
    for (int s = 128; s > 0; s >>= 1) { if (tid < s) red[tid] += red[tid+s]; __syncthreads(); }
    float inv = 1.f / red[0];
    v.x *= inv; v.y *= inv; v.z *= inv; v.w *= inv;
    *reinterpret_cast<float4*>(p + tid*4) = v;
}

// ---------------- attn @ V, writes directly into (B,S,D) layout ----------
__global__ void attn_pv_kernel(const float* __restrict__ sc, const float* __restrict__ v,
                               float* __restrict__ out) {
    int bh = blockIdx.y;
    int b = bh / HH, h = bh % HH;
    int q0 = blockIdx.x * 64;
    int tid = threadIdx.x;
    int tx = tid & 15, ty = tid >> 4;

    __shared__ float Ps[16][65];
    __shared__ float Vs[16][64];
    float acc[4][4];
    #pragma unroll
    for (int i=0;i<4;i++)
        #pragma unroll
        for (int j=0;j<4;j++) acc[i][j]=0.f;

    int kmax = q0 + 64;  // softmax rows are zero beyond the diagonal
    for (int kt = 0; kt < kmax; kt += 16) {
        {
            int qr = tid >> 2, kk = (tid & 3) * 4;
            float4 pv = *reinterpret_cast<const float4*>(sc + ((size_t)bh*SS + q0 + qr)*SS + kt + kk);
            Ps[kk+0][qr]=pv.x; Ps[kk+1][qr]=pv.y; Ps[kk+2][qr]=pv.z; Ps[kk+3][qr]=pv.w;
        }
        #pragma unroll
        for (int t = 0; t < 4; t++) {
            int idx = tid + t*256;
            int kk = idx >> 6, d = idx & 63;
            Vs[kk][d] = v[(size_t)(b*SS + kt + kk)*DD + h*HDD + d];
        }
        __syncthreads();
        #pragma unroll
        for (int kk = 0; kk < 16; kk++) {
            float ra[4], rb[4];
            #pragma unroll
            for (int i = 0; i < 4; i++) ra[i] = Ps[kk][ty*4+i];
            #pragma unroll
            for (int j = 0; j < 4; j++) rb[j] = Vs[kk][tx*4+j];
            #pragma unroll
            for (int i = 0; i < 4; i++)
                #pragma unroll
                for (int j = 0; j < 4; j++) acc[i][j] = fmaf(ra[i], rb[j], acc[i][j]);
        }
        __syncthreads();
    }
    #pragma unroll
    for (int i = 0; i < 4; i++)
        #pragma unroll
        for (int j = 0; j < 4; j++)
            out[(size_t)(b*SS + q0 + ty*4 + i)*DD + h*HDD + tx*4 + j] = acc[i][j];
}

// ---------------- launch ----------------
extern "C" void kernel_launch(void* const* d_in, const int* in_sizes, int n_in,
                              void* d_out, int out_size) {
    const int*   ids   = (const int*)  d_in[0];
    const float* amask = (const float*)d_in[1];
    const float* tok   = (const float*)d_in[2];
    const float* pemb  = (const float*)d_in[3];
    const float* ln1g  = (const float*)d_in[4];
    const float* ln1b  = (const float*)d_in[5];
    const float* Wq    = (const float*)d_in[6];
    const float* bq    = (const float*)d_in[7];
    const float* Wk    = (const float*)d_in[8];
    const float* bk    = (const float*)d_in[9];
    const float* Wv    = (const float*)d_in[10];
    const float* bv    = (const float*)d_in[11];
    const float* Wp    = (const float*)d_in[12];
    const float* bp    = (const float*)d_in[13];
    const float* ln2g  = (const float*)d_in[14];
    const float* ln2b  = (const float*)d_in[15];
    const float* W1    = (const float*)d_in[16];
    const float* b1    = (const float*)d_in[17];
    const float* W2    = (const float*)d_in[18];
    const float* b2    = (const float*)d_in[19];
    const float* lnfg  = (const float*)d_in[20];
    const float* lnfb  = (const float*)d_in[21];
    float* out = (float*)d_out;

    float *xp, *hp, *qp, *kp, *vp, *ap, *fp, *scp; int* pidp;
    cudaGetSymbolAddress((void**)&xp,  g_x);
    cudaGetSymbolAddress((void**)&hp,  g_h);
    cudaGetSymbolAddress((void**)&qp,  g_q);
    cudaGetSymbolAddress((void**)&kp,  g_k);
    cudaGetSymbolAddress((void**)&vp,  g_v);
    cudaGetSymbolAddress((void**)&ap,  g_attn);
    cudaGetSymbolAddress((void**)&fp,  g_ff);
    cudaGetSymbolAddress((void**)&scp, g_scores);
    cudaGetSymbolAddress((void**)&pidp, g_pos);

    posids_kernel<<<BB, 32>>>(amask, pidp);
    embed_kernel<<<MM, 256>>>(ids, pidp, tok, pemb, xp);

    dim3 gD((DD+127)/128, MM/128);     // 6 x 16
    dim3 gF((FF+127)/128, MM/128);     // 24 x 16
    dim3 gV((VV+127)/128, MM/128);     // 393 x 16
    dim3 gSc(SS/64, SS/64, BB*HH);     // 16 x 16 x 24
    dim3 gPv(SS/64, BB*HH);            // 16 x 24

    for (int l = 0; l < LL; l++) {
        const float* wq = Wq + (size_t)l*DD*DD;  const float* bqv = bq + l*DD;
        const float* wk = Wk + (size_t)l*DD*DD;  const float* bkv = bk + l*DD;
        const float* wv = Wv + (size_t)l*DD*DD;  const float* bvv = bv + l*DD;
        const float* wp = Wp + (size_t)l*DD*DD;  const float* bpv = bp + l*DD;
        const float* w1 = W1 + (size_t)l*DD*FF;  const float* b1v = b1 + l*FF;
        const float* w2 = W2 + (size_t)l*FF*DD;  const float* b2v = b2 + l*DD;

        layernorm_kernel<<<MM, 256>>>(xp, ln1g + l*DD, ln1b + l*DD, hp);
        sgemm_kernel<0><<<gD, 256>>>(hp, wq, bqv, nullptr, qp, MM, DD, DD, 0);
        sgemm_kernel<0><<<gD, 256>>>(hp, wk, bkv, nullptr, kp, MM, DD, DD, 0);
        sgemm_kernel<0><<<gD, 256>>>(hp, wv, bvv, nullptr, vp, MM, DD, DD, 0);
        attn_scores_kernel<<<gSc, 256>>>(qp, kp, amask, scp);
        softmax_kernel<<<BB*HH*SS, 256>>>(scp);
        attn_pv_kernel<<<gPv, 256>>>(scp, vp, ap);
        sgemm_kernel<0><<<gD, 256>>>(ap, wp, bpv, xp, xp, MM, DD, DD, 0);
        layernorm_kernel<<<MM, 256>>>(xp, ln2g + l*DD, ln2b + l*DD, hp);
        sgemm_kernel<0><<<gF, 256>>>(hp, w1, b1v, nullptr, fp, MM, FF, DD, 1);
        sgemm_kernel<0><<<gD, 256>>>(fp, w2, b2v, xp, xp, MM, DD, FF, 0);
    }

    layernorm_kernel<<<MM, 256>>>(xp, lnfg, lnfb, hp);
    sgemm_kernel<1><<<gV, 256>>>(hp, tok, nullptr, nullptr, out, MM, VV, DD, 0);
}

// round 4
// speedup vs baseline: 2.6001x; 2.6001x over previous
#include <cuda_runtime.h>
#include <cuda_bf16.h>
#include <math.h>
#include <stdint.h>

#define BB 2
#define SS 1024
#define DD 768
#define HH 12
#define HDD 64
#define LL 12
#define VV 50257
#define FF 3072
#define MM (BB*SS)   // 2048

// ---------------- scratch (allocation-free) ----------------
__device__ float g_x[MM*DD];
__device__ float g_h[MM*DD];
__device__ float g_q[MM*DD];
__device__ float g_k[MM*DD];
__device__ float g_v[MM*DD];
__device__ float g_attn[MM*DD];
__device__ float g_ff[MM*FF];
__device__ float g_scores[(size_t)BB*HH*SS*SS];
__device__ int   g_pos[BB*SS];

// ================= helpers =================
__device__ __forceinline__ uint32_t smem_u32(const void* p) {
    uint32_t a;
    asm("{ .reg .u64 t; cvta.to.shared.u64 t, %1; cvt.u32.u64 %0, t; }" : "=r"(a) : "l"(p));
    return a;
}

__device__ __forceinline__ void ldsm_x4(uint32_t& r0, uint32_t& r1, uint32_t& r2, uint32_t& r3,
                                        uint32_t addr) {
    asm volatile("ldmatrix.sync.aligned.m8n8.x4.shared.b16 {%0,%1,%2,%3}, [%4];"
                 : "=r"(r0), "=r"(r1), "=r"(r2), "=r"(r3) : "r"(addr));
}
__device__ __forceinline__ void ldsm_x4_t(uint32_t& r0, uint32_t& r1, uint32_t& r2, uint32_t& r3,
                                          uint32_t addr) {
    asm volatile("ldmatrix.sync.aligned.m8n8.x4.trans.shared.b16 {%0,%1,%2,%3}, [%4];"
                 : "=r"(r0), "=r"(r1), "=r"(r2), "=r"(r3) : "r"(addr));
}
__device__ __forceinline__ void mma16816(float* c, const uint32_t* a, const uint32_t* b) {
    asm volatile("mma.sync.aligned.m16n8k16.row.col.f32.bf16.bf16.f32 "
                 "{%0,%1,%2,%3}, {%4,%5,%6,%7}, {%8,%9}, {%0,%1,%2,%3};"
                 : "+f"(c[0]), "+f"(c[1]), "+f"(c[2]), "+f"(c[3])
                 : "r"(a[0]), "r"(a[1]), "r"(a[2]), "r"(a[3]), "r"(b[0]), "r"(b[1]));
}

__device__ __forceinline__ void split4(float4 v, uint2& hi, uint2& lo) {
    __nv_bfloat16 h0 = __float2bfloat16(v.x), h1 = __float2bfloat16(v.y);
    __nv_bfloat16 h2 = __float2bfloat16(v.z), h3 = __float2bfloat16(v.w);
    __nv_bfloat16 l0 = __float2bfloat16(v.x - __bfloat162float(h0));
    __nv_bfloat16 l1 = __float2bfloat16(v.y - __bfloat162float(h1));
    __nv_bfloat16 l2 = __float2bfloat16(v.z - __bfloat162float(h2));
    __nv_bfloat16 l3 = __float2bfloat16(v.w - __bfloat162float(h3));
    __nv_bfloat162 a = __nv_bfloat162(h0, h1), b = __nv_bfloat162(h2, h3);
    __nv_bfloat162 c = __nv_bfloat162(l0, l1), d = __nv_bfloat162(l2, l3);
    hi.x = *(uint32_t*)&a; hi.y = *(uint32_t*)&b;
    lo.x = *(uint32_t*)&c; lo.y = *(uint32_t*)&d;
}

__device__ __forceinline__ float gelu_exact(float v) {
    return 0.5f * v * (1.0f + erff(v * 0.70710678118654752f));
}

// ============ mma.sync split-bf16 GEMM ============
// C(MxN) = A(MxK)@B + bias [+gelu] [+res]; fp32-equivalent via hh+hl+lh bf16 MMAs.
// TRANSB=0: B stored (K,N) row-major. TRANSB=1: B stored (N,K) row-major.
// CTA 256 thr, tile 128x128, BK=32, warp tile 32x64 (warps 4x2).
#define SA_LO 10240
#define SB_HI 20480

template<int TRANSB>
__global__ void __launch_bounds__(256, 1)
mma_gemm(const float* __restrict__ A, const float* __restrict__ Bw,
         const float* __restrict__ bias, const float* __restrict__ res,
         float* __restrict__ C, int M, int N, int K, int act)
{
    __shared__ __align__(16) unsigned char sm[SB_HI + 2*10240];
    constexpr int BLO = TRANSB ? 10240 : 8704;
    const uint32_t sbase = smem_u32(sm);
    const int tid = threadIdx.x, lane = tid & 31, wid = tid >> 5;
    const int wm = wid & 3, wn = wid >> 2;
    const int m0 = blockIdx.y << 7, n0 = blockIdx.x << 7;
    const int grp = lane >> 2, tig = lane & 3;

    float acc[2][8][4];
    #pragma unroll
    for (int i = 0; i < 2; i++)
        #pragma unroll
        for (int j = 0; j < 8; j++)
            #pragma unroll
            for (int q = 0; q < 4; q++) acc[i][j][q] = 0.f;

    const int arow = tid >> 3, ak4 = tid & 7;
    const float* pa = A + (size_t)(m0 + arow) * K + ak4 * 4;

    const float* pb;
    bool bpred[4];
    if (TRANSB) {
        #pragma unroll
        for (int p = 0; p < 4; p++) bpred[p] = (n0 + arow + 32*p) < N;
        pb = Bw + (size_t)(n0 + arow) * K + ak4 * 4;
    } else {
        #pragma unroll
        for (int p = 0; p < 4; p++) bpred[p] = true;
        pb = Bw + (size_t)(tid >> 5) * N + n0 + (tid & 31) * 4;
    }

    const int NC = K >> 5;
    float4 ra[4], rb[4];
    const float4 z4 = make_float4(0.f, 0.f, 0.f, 0.f);

    // preload chunk 0
    #pragma unroll
    for (int p = 0; p < 4; p++) {
        ra[p] = *(const float4*)(pa + (size_t)(32*p) * K);
        if (TRANSB) rb[p] = bpred[p] ? *(const float4*)(pb + (size_t)(32*p) * K) : z4;
        else        rb[p] = *(const float4*)(pb + (size_t)(8*p) * N);
    }

    for (int kc = 0; kc < NC; kc++) {
        // ---- convert + store SMEM ----
        #pragma unroll
        for (int p = 0; p < 4; p++) {
            uint2 hi, lo;
            split4(ra[p], hi, lo);
            uint32_t aoff = (uint32_t)(arow + 32*p) * 80u + (uint32_t)ak4 * 8u;
            *(uint2*)(sm + aoff)         = hi;
            *(uint2*)(sm + SA_LO + aoff) = lo;
            split4(rb[p], hi, lo);
            uint32_t boff;
            if (TRANSB) boff = (uint32_t)(arow + 32*p) * 80u + (uint32_t)ak4 * 8u;
            else        boff = (uint32_t)((tid >> 5) + 8*p) * 272u + (uint32_t)(tid & 31) * 8u;
            *(uint2*)(sm + SB_HI + boff)       = hi;
            *(uint2*)(sm + SB_HI + BLO + boff) = lo;
        }
        __syncthreads();

        // ---- prefetch next chunk ----
        if (kc + 1 < NC) {
            const int koff = (kc + 1) * 32;
            #pragma unroll
            for (int p = 0; p < 4; p++) {
                ra[p] = *(const float4*)(pa + (size_t)(32*p) * K + koff);
                if (TRANSB) rb[p] = bpred[p] ? *(const float4*)(pb + (size_t)(32*p) * K + koff) : z4;
                else        rb[p] = *(const float4*)(pb + ((size_t)(8*p) + (size_t)koff) * N);
            }
        }

        // ---- compute: 2 k-steps of 16 ----
        #pragma unroll
        for (int ks = 0; ks < 2; ks++) {
            uint32_t ah[2][4], al[2][4], bh[8][2], bl[8][2];
            #pragma unroll
            for (int mt = 0; mt < 2; mt++) {
                uint32_t addr = sbase + (uint32_t)(wm*32 + mt*16 + (lane & 15)) * 80u
                              + (uint32_t)(ks*32) + ((lane >> 4) << 4);
                ldsm_x4(ah[mt][0], ah[mt][1], ah[mt][2], ah[mt][3], addr);
                ldsm_x4(al[mt][0], al[mt][1], al[mt][2], al[mt][3], addr + SA_LO);
            }
            #pragma unroll
            for (int ntp = 0; ntp < 4; ntp++) {
                uint32_t r0, r1, r2, r3;
                if (TRANSB) {
                    uint32_t addr = sbase + SB_HI
                                  + (uint32_t)(wn*64 + ntp*16 + (lane & 15)) * 80u
                                  + (uint32_t)(ks*32) + ((lane >> 4) << 4);
                    ldsm_x4(r0, r1, r2, r3, addr);
                    bh[2*ntp][0] = r0; bh[2*ntp+1][0] = r1;
                    bh[2*ntp][1] = r2; bh[2*ntp+1][1] = r3;
                    ldsm_x4(r0, r1, r2, r3, addr + BLO);
                    bl[2*ntp][0] = r0; bl[2*ntp+1][0] = r1;
                    bl[2*ntp][1] = r2; bl[2*ntp+1][1] = r3;
                } else {
                    uint32_t addr = sbase + SB_HI
                                  + (uint32_t)(ks*16 + (lane & 15)) * 272u
                                  + (uint32_t)(wn*64 + ntp*16) * 2u + ((lane >> 4) << 4);
                    ldsm_x4_t(r0, r1, r2, r3, addr);
                    bh[2*ntp][0] = r0; bh[2*ntp][1] = r1;
                    bh[2*ntp+1][0] = r2; bh[2*ntp+1][1] = r3;
                    ldsm_x4_t(r0, r1, r2, r3, addr + BLO);
                    bl[2*ntp][0] = r0; bl[2*ntp][1] = r1;
                    bl[2*ntp+1][0] = r2; bl[2*ntp+1][1] = r3;
                }
            }
            #pragma unroll
            for (int mt = 0; mt < 2; mt++)
                #pragma unroll
                for (int nt = 0; nt < 8; nt++) {
                    mma16816(acc[mt][nt], ah[mt], bh[nt]);
                    mma16816(acc[mt][nt], ah[mt], bl[nt]);
                    mma16816(acc[mt][nt], al[mt], bh[nt]);
                }
        }
        __syncthreads();
    }

    // ---- epilogue: bias / gelu / residual ----
    // float2 stores only when TRANSB==0 (N even, col even => 8B aligned).
    // LM head (TRANSB==1, N=50257 odd) uses scalar stores.
    const int mrow = m0 + wm*32;
    #pragma unroll
    for (int mt = 0; mt < 2; mt++) {
        #pragma unroll
        for (int nt = 0; nt < 8; nt++) {
            int col = n0 + wn*64 + nt*8 + tig*2;
            bool ok0 = (!TRANSB) || (col < N);
            bool ok1 = (!TRANSB) || (col + 1 < N);
            float b0v = 0.f, b1v = 0.f;
            if (bias) { if (ok0) b0v = bias[col]; if (ok1) b1v = bias[col+1]; }
            #pragma unroll
            for (int hh = 0; hh < 2; hh++) {
                int row = mrow + mt*16 + grp + hh*8;
                float v0 = acc[mt][nt][2*hh+0] + b0v;
                float v1 = acc[mt][nt][2*hh+1] + b1v;
                if (act) { v0 = gelu_exact(v0); v1 = gelu_exact(v1); }
                size_t base = (size_t)row * N + col;
                if (res) { if (ok0) v0 += res[base]; if (ok1) v1 += res[base+1]; }
                if (!TRANSB) {
                    float2 o; o.x = v0; o.y = v1;
                    *(float2*)(C + base) = o;
                } else {
                    if (ok0) C[base] = v0;
                    if (ok1) C[base+1] = v1;
                }
            }
        }
    }
}

// ---------------- position ids ----------------
__global__ void posids_kernel(const float* __restrict__ amask, int* __restrict__ pos) {
    int b = blockIdx.x;
    if (threadIdx.x == 0) {
        float c = 0.f;
        for (int s = 0; s < SS; s++) {
            float m = amask[b*SS + s];
            c += m;
            pos[b*SS + s] = (m == 0.f) ? 0 : (int)(c - 1.f);
        }
    }
}

// ---------------- embedding ----------------
__global__ void embed_kernel(const int* __restrict__ ids, const int* __restrict__ pos,
                             const float* __restrict__ tok, const float* __restrict__ pemb,
                             float* __restrict__ x) {
    int row = blockIdx.x;
    int id = ids[row];
    int p  = pos[row];
    int tid = threadIdx.x;
    #pragma unroll
    for (int t = 0; t < 3; t++) {
        int d = tid + t*256;
        x[(size_t)row*DD + d] = tok[(size_t)id*DD + d] + pemb[(size_t)p*DD + d];
    }
}

// ---------------- layernorm ----------------
__global__ void layernorm_kernel(const float* __restrict__ x, const float* __restrict__ g,
                                 const float* __restrict__ b, float* __restrict__ y) {
    __shared__ float red[256];
    int row = blockIdx.x;
    int tid = threadIdx.x;
    const float* xr = x + (size_t)row*DD;
    float v0 = xr[tid], v1 = xr[tid+256], v2 = xr[tid+512];
    red[tid] = v0 + v1 + v2;
    __syncthreads();
    for (int s = 128; s > 0; s >>= 1) { if (tid < s) red[tid] += red[tid+s]; __syncthreads(); }
    float mu = red[0] * (1.f/DD);
    __syncthreads();
    float d0 = v0-mu, d1 = v1-mu, d2 = v2-mu;
    red[tid] = d0*d0 + d1*d1 + d2*d2;
    __syncthreads();
    for (int s = 128; s > 0; s >>= 1) { if (tid < s) red[tid] += red[tid+s]; __syncthreads(); }
    float rstd = rsqrtf(red[0] * (1.f/DD) + 1e-5f);
    float* yr = y + (size_t)row*DD;
    yr[tid]     = d0*rstd*g[tid]     + b[tid];
    yr[tid+256] = d1*rstd*g[tid+256] + b[tid+256];
    yr[tid+512] = d2*rstd*g[tid+512] + b[tid+512];
}

// ---------------- attention scores ----------------
__global__ void attn_scores_kernel(const float* __restrict__ q, const float* __restrict__ k,
                                   const float* __restrict__ amask, float* __restrict__ sc) {
    int bh = blockIdx.z;
    int b = bh / HH, h = bh % HH;
    int q0 = blockIdx.y * 64, k0 = blockIdx.x * 64;
    int tid = threadIdx.x;
    int tx = tid & 15, ty = tid >> 4;

    if (k0 > q0 + 63) {
        #pragma unroll
        for (int i = 0; i < 4; i++)
            #pragma unroll
            for (int j = 0; j < 4; j++)
                sc[((size_t)bh*SS + q0 + ty*4 + i)*SS + k0 + tx*4 + j] = -1e30f;
        return;
    }

    __shared__ float Qs[64][65];
    __shared__ float Ks[64][65];
    #pragma unroll
    for (int t = 0; t < 16; t++) {
        int idx = tid + t*256;
        int r = idx >> 6, d = idx & 63;
        Qs[d][r] = q[(size_t)(b*SS + q0 + r)*DD + h*HDD + d];
        Ks[d][r] = k[(size_t)(b*SS + k0 + r)*DD + h*HDD + d];
    }
    __syncthreads();

    float acc[4][4];
    #pragma unroll
    for (int i=0;i<4;i++)
        #pragma unroll
        for (int j=0;j<4;j++) acc[i][j]=0.f;
    #pragma unroll 8
    for (int d = 0; d < 64; d++) {
        float rav[4], rbv[4];
        #pragma unroll
        for (int i = 0; i < 4; i++) rav[i] = Qs[d][ty*4+i];
        #pragma unroll
        for (int j = 0; j < 4; j++) rbv[j] = Ks[d][tx*4+j];
        #pragma unroll
        for (int i = 0; i < 4; i++)
            #pragma unroll
            for (int j = 0; j < 4; j++) acc[i][j] = fmaf(rav[i], rbv[j], acc[i][j]);
    }
    const float scale = 0.125f;
    #pragma unroll
    for (int i = 0; i < 4; i++) {
        int qr = q0 + ty*4 + i;
        #pragma unroll
        for (int j = 0; j < 4; j++) {
            int kc = k0 + tx*4 + j;
            bool ok = (kc <= qr) && (amask[b*SS + kc] != 0.f);
            sc[((size_t)bh*SS + qr)*SS + kc] = ok ? acc[i][j]*scale : -1e30f;
        }
    }
}

// ---------------- rowwise softmax ----------------
__global__ void softmax_kernel(float* __restrict__ sc) {
    __shared__ float red[256];
    size_t row = blockIdx.x;
    float* p = sc + row*SS;
    int tid = threadIdx.x;
    float4 v = *reinterpret_cast<float4*>(p + tid*4);
    float mx = fmaxf(fmaxf(v.x, v.y), fmaxf(v.z, v.w));
    red[tid] = mx; __syncthreads();
    for (int s = 128; s > 0; s >>= 1) { if (tid < s) red[tid] = fmaxf(red[tid], red[tid+s]); __syncthreads(); }
    mx = red[0]; __syncthreads();
    v.x = __expf(v.x - mx); v.y = __expf(v.y - mx); v.z = __expf(v.z - mx); v.w = __expf(v.w - mx);
    red[tid] = v.x + v.y + v.z + v.w; __syncthreads();
    for (int s = 128; s > 0; s >>= 1) { if (tid < s) red[tid] += red[tid+s]; __syncthreads(); }
    float inv = 1.f / red[0];
    v.x *= inv; v.y *= inv; v.z *= inv; v.w *= inv;
    *reinterpret_cast<float4*>(p + tid*4) = v;
}

// ---------------- attn @ V ----------------
__global__ void attn_pv_kernel(const float* __restrict__ sc, const float* __restrict__ v,
                               float* __restrict__ out) {
    int bh = blockIdx.y;
    int b = bh / HH, h = bh % HH;
    int q0 = blockIdx.x * 64;
    int tid = threadIdx.x;
    int tx = tid & 15, ty = tid >> 4;

    __shared__ float Ps[16][65];
    __shared__ float Vs[16][64];
    float acc[4][4];
    #pragma unroll
    for (int i=0;i<4;i++)
        #pragma unroll
        for (int j=0;j<4;j++) acc[i][j]=0.f;

    int kmax = q0 + 64;
    for (int kt = 0; kt < kmax; kt += 16) {
        {
            int qr = tid >> 2, kk = (tid & 3) * 4;
            float4 pv = *reinterpret_cast<const float4*>(sc + ((size_t)bh*SS + q0 + qr)*SS + kt + kk);
            Ps[kk+0][qr]=pv.x; Ps[kk+1][qr]=pv.y; Ps[kk+2][qr]=pv.z; Ps[kk+3][qr]=pv.w;
        }
        #pragma unroll
        for (int t = 0; t < 4; t++) {
            int idx = tid + t*256;
            int kk = idx >> 6, d = idx & 63;
            Vs[kk][d] = v[(size_t)(b*SS + kt + kk)*DD + h*HDD + d];
        }
        __syncthreads();
        #pragma unroll
        for (int kk = 0; kk < 16; kk++) {
            float rav[4], rbv[4];
            #pragma unroll
            for (int i = 0; i < 4; i++) rav[i] = Ps[kk][ty*4+i];
            #pragma unroll
            for (int j = 0; j < 4; j++) rbv[j] = Vs[kk][tx*4+j];
            #pragma unroll
            for (int i = 0; i < 4; i++)
                #pragma unroll
                for (int j = 0; j < 4; j++) acc[i][j] = fmaf(rav[i], rbv[j], acc[i][j]);
        }
        __syncthreads();
    }
    #pragma unroll
    for (int i = 0; i < 4; i++)
        #pragma unroll
        for (int j = 0; j < 4; j++)
            out[(size_t)(b*SS + q0 + ty*4 + i)*DD + h*HDD + tx*4 + j] = acc[i][j];
}

// ---------------- launch ----------------
extern "C" void kernel_launch(void* const* d_in, const int* in_sizes, int n_in,
                              void* d_out, int out_size) {
    const int*   ids   = (const int*)  d_in[0];
    const float* amask = (const float*)d_in[1];
    const float* tok   = (const float*)d_in[2];
    const float* pemb  = (const float*)d_in[3];
    const float* ln1g  = (const float*)d_in[4];
    const float* ln1b  = (const float*)d_in[5];
    const float* Wq    = (const float*)d_in[6];
    const float* bq    = (const float*)d_in[7];
    const float* Wk    = (const float*)d_in[8];
    const float* bk    = (const float*)d_in[9];
    const float* Wv    = (const float*)d_in[10];
    const float* bv    = (const float*)d_in[11];
    const float* Wp    = (const float*)d_in[12];
    const float* bp    = (const float*)d_in[13];
    const float* ln2g  = (const float*)d_in[14];
    const float* ln2b  = (const float*)d_in[15];
    const float* W1    = (const float*)d_in[16];
    const float* b1    = (const float*)d_in[17];
    const float* W2    = (const float*)d_in[18];
    const float* b2    = (const float*)d_in[19];
    const float* lnfg  = (const float*)d_in[20];
    const float* lnfb  = (const float*)d_in[21];
    float* out = (float*)d_out;

    float *xp, *hp, *qp, *kp, *vp, *ap, *fp, *scp; int* pidp;
    cudaGetSymbolAddress((void**)&xp,  g_x);
    cudaGetSymbolAddress((void**)&hp,  g_h);
    cudaGetSymbolAddress((void**)&qp,  g_q);
    cudaGetSymbolAddress((void**)&kp,  g_k);
    cudaGetSymbolAddress((void**)&vp,  g_v);
    cudaGetSymbolAddress((void**)&ap,  g_attn);
    cudaGetSymbolAddress((void**)&fp,  g_ff);
    cudaGetSymbolAddress((void**)&scp, g_scores);
    cudaGetSymbolAddress((void**)&pidp, g_pos);

    posids_kernel<<<BB, 32>>>(amask, pidp);
    embed_kernel<<<MM, 256>>>(ids, pidp, tok, pemb, xp);

    dim3 gD(DD/128, MM/128);           // 6 x 16
    dim3 gF(FF/128, MM/128);           // 24 x 16
    dim3 gV((VV+127)/128, MM/128);     // 393 x 16
    dim3 gSc(SS/64, SS/64, BB*HH);
    dim3 gPv(SS/64, BB*HH);

    for (int l = 0; l < LL; l++) {
        const float* wq = Wq + (size_t)l*DD*DD;  const float* bqv = bq + l*DD;
        const float* wk = Wk + (size_t)l*DD*DD;  const float* bkv = bk + l*DD;
        const float* wv = Wv + (size_t)l*DD*DD;  const float* bvv = bv + l*DD;
        const float* wp = Wp + (size_t)l*DD*DD;  const float* bpv = bp + l*DD;
        const float* w1 = W1 + (size_t)l*DD*FF;  const float* b1v = b1 + l*FF;
        const float* w2 = W2 + (size_t)l*FF*DD;  const float* b2v = b2 + l*DD;

        layernorm_kernel<<<MM, 256>>>(xp, ln1g + l*DD, ln1b + l*DD, hp);
        mma_gemm<0><<<gD, 256>>>(hp, wq, bqv, nullptr, qp, MM, DD, DD, 0);
        mma_gemm<0><<<gD, 256>>>(hp, wk, bkv, nullptr, kp, MM, DD, DD, 0);
        mma_gemm<0><<<gD, 256>>>(hp, wv, bvv, nullptr, vp, MM, DD, DD, 0);
        attn_scores_kernel<<<gSc, 256>>>(qp, kp, amask, scp);
        softmax_kernel<<<BB*HH*SS, 256>>>(scp);
        attn_pv_kernel<<<gPv, 256>>>(scp, vp, ap);
        mma_gemm<0><<<gD, 256>>>(ap, wp, bpv, xp, xp, MM, DD, DD, 0);
        layernorm_kernel<<<MM, 256>>>(xp, ln2g + l*DD, ln2b + l*DD, hp);
        mma_gemm<0><<<gF, 256>>>(hp, w1, b1v, nullptr, fp, MM, FF, DD, 1);
        mma_gemm<0><<<gD, 256>>>(fp, w2, b2v, xp, xp, MM, DD, FF, 0);
    }

    layernorm_kernel<<<MM, 256>>>(xp, lnfg, lnfb, hp);
    mma_gemm<1><<<gV, 256>>>(hp, tok, nullptr, nullptr, out, MM, VV, DD, 0);
}

// round 5
// speedup vs baseline: 3.4517x; 1.3275x over previous
#include <cuda_runtime.h>
#include <cuda_bf16.h>
#include <math.h>
#include <stdint.h>

#define BB 2
#define SS 1024
#define DD 768
#define HH 12
#define HDD 64
#define LL 12
#define VV 50257
#define FF 3072
#define MM (BB*SS)   // 2048

// ---------------- scratch (allocation-free) ----------------
__device__ float g_x[MM*DD];
__device__ float g_h[MM*DD];
__device__ float g_qkv[MM*3*DD];
__device__ float g_attn[MM*DD];
__device__ float g_ff[MM*FF];
__device__ int   g_pos[BB*SS];

// ================= helpers =================
__device__ __forceinline__ uint32_t smem_u32(const void* p) {
    uint32_t a;
    asm("{ .reg .u64 t; cvta.to.shared.u64 t, %1; cvt.u32.u64 %0, t; }" : "=r"(a) : "l"(p));
    return a;
}

__device__ __forceinline__ void ldsm_x4(uint32_t& r0, uint32_t& r1, uint32_t& r2, uint32_t& r3,
                                        uint32_t addr) {
    asm volatile("ldmatrix.sync.aligned.m8n8.x4.shared.b16 {%0,%1,%2,%3}, [%4];"
                 : "=r"(r0), "=r"(r1), "=r"(r2), "=r"(r3) : "r"(addr));
}
__device__ __forceinline__ void ldsm_x4_t(uint32_t& r0, uint32_t& r1, uint32_t& r2, uint32_t& r3,
                                          uint32_t addr) {
    asm volatile("ldmatrix.sync.aligned.m8n8.x4.trans.shared.b16 {%0,%1,%2,%3}, [%4];"
                 : "=r"(r0), "=r"(r1), "=r"(r2), "=r"(r3) : "r"(addr));
}
__device__ __forceinline__ void mma16816(float* c, const uint32_t* a, const uint32_t* b) {
    asm volatile("mma.sync.aligned.m16n8k16.row.col.f32.bf16.bf16.f32 "
                 "{%0,%1,%2,%3}, {%4,%5,%6,%7}, {%8,%9}, {%0,%1,%2,%3};"
                 : "+f"(c[0]), "+f"(c[1]), "+f"(c[2]), "+f"(c[3])
                 : "r"(a[0]), "r"(a[1]), "r"(a[2]), "r"(a[3]), "r"(b[0]), "r"(b[1]));
}

__device__ __forceinline__ void split4(float4 v, uint2& hi, uint2& lo) {
    __nv_bfloat16 h0 = __float2bfloat16(v.x), h1 = __float2bfloat16(v.y);
    __nv_bfloat16 h2 = __float2bfloat16(v.z), h3 = __float2bfloat16(v.w);
    __nv_bfloat16 l0 = __float2bfloat16(v.x - __bfloat162float(h0));
    __nv_bfloat16 l1 = __float2bfloat16(v.y - __bfloat162float(h1));
    __nv_bfloat16 l2 = __float2bfloat16(v.z - __bfloat162float(h2));
    __nv_bfloat16 l3 = __float2bfloat16(v.w - __bfloat162float(h3));
    __nv_bfloat162 a = __nv_bfloat162(h0, h1), b = __nv_bfloat162(h2, h3);
    __nv_bfloat162 c = __nv_bfloat162(l0, l1), d = __nv_bfloat162(l2, l3);
    hi.x = *(uint32_t*)&a; hi.y = *(uint32_t*)&b;
    lo.x = *(uint32_t*)&c; lo.y = *(uint32_t*)&d;
}
__device__ __forceinline__ void split2(float a, float b, uint32_t& hi, uint32_t& lo) {
    __nv_bfloat16 h0 = __float2bfloat16(a), h1 = __float2bfloat16(b);
    __nv_bfloat16 l0 = __float2bfloat16(a - __bfloat162float(h0));
    __nv_bfloat16 l1 = __float2bfloat16(b - __bfloat162float(h1));
    __nv_bfloat162 H(h0, h1), L(l0, l1);
    hi = *(uint32_t*)&H; lo = *(uint32_t*)&L;
}

__device__ __forceinline__ float gelu_exact(float v) {
    return 0.5f * v * (1.0f + erff(v * 0.70710678118654752f));
}

// ============ mma.sync split-bf16 GEMM (as R4) ============
#define SA_LO 10240
#define SB_HI 20480

template<int TRANSB>
__global__ void __launch_bounds__(256, 1)
mma_gemm(const float* __restrict__ A, const float* __restrict__ Bw,
         const float* __restrict__ bias, const float* __restrict__ res,
         float* __restrict__ C, int M, int N, int K, int act)
{
    __shared__ __align__(16) unsigned char sm[SB_HI + 2*10240];
    constexpr int BLO = TRANSB ? 10240 : 8704;
    const uint32_t sbase = smem_u32(sm);
    const int tid = threadIdx.x, lane = tid & 31, wid = tid >> 5;
    const int wm = wid & 3, wn = wid >> 2;
    const int m0 = blockIdx.y << 7, n0 = blockIdx.x << 7;
    const int grp = lane >> 2, tig = lane & 3;

    float acc[2][8][4];
    #pragma unroll
    for (int i = 0; i < 2; i++)
        #pragma unroll
        for (int j = 0; j < 8; j++)
            #pragma unroll
            for (int q = 0; q < 4; q++) acc[i][j][q] = 0.f;

    const int arow = tid >> 3, ak4 = tid & 7;
    const float* pa = A + (size_t)(m0 + arow) * K + ak4 * 4;

    const float* pb;
    bool bpred[4];
    if (TRANSB) {
        #pragma unroll
        for (int p = 0; p < 4; p++) bpred[p] = (n0 + arow + 32*p) < N;
        pb = Bw + (size_t)(n0 + arow) * K + ak4 * 4;
    } else {
        #pragma unroll
        for (int p = 0; p < 4; p++) bpred[p] = true;
        pb = Bw + (size_t)(tid >> 5) * N + n0 + (tid & 31) * 4;
    }

    const int NC = K >> 5;
    float4 ra[4], rb[4];
    const float4 z4 = make_float4(0.f, 0.f, 0.f, 0.f);

    #pragma unroll
    for (int p = 0; p < 4; p++) {
        ra[p] = *(const float4*)(pa + (size_t)(32*p) * K);
        if (TRANSB) rb[p] = bpred[p] ? *(const float4*)(pb + (size_t)(32*p) * K) : z4;
        else        rb[p] = *(const float4*)(pb + (size_t)(8*p) * N);
    }

    for (int kc = 0; kc < NC; kc++) {
        #pragma unroll
        for (int p = 0; p < 4; p++) {
            uint2 hi, lo;
            split4(ra[p], hi, lo);
            uint32_t aoff = (uint32_t)(arow + 32*p) * 80u + (uint32_t)ak4 * 8u;
            *(uint2*)(sm + aoff)         = hi;
            *(uint2*)(sm + SA_LO + aoff) = lo;
            split4(rb[p], hi, lo);
            uint32_t boff;
            if (TRANSB) boff = (uint32_t)(arow + 32*p) * 80u + (uint32_t)ak4 * 8u;
            else        boff = (uint32_t)((tid >> 5) + 8*p) * 272u + (uint32_t)(tid & 31) * 8u;
            *(uint2*)(sm + SB_HI + boff)       = hi;
            *(uint2*)(sm + SB_HI + BLO + boff) = lo;
        }
        __syncthreads();

        if (kc + 1 < NC) {
            const int koff = (kc + 1) * 32;
            #pragma unroll
            for (int p = 0; p < 4; p++) {
                ra[p] = *(const float4*)(pa + (size_t)(32*p) * K + koff);
                if (TRANSB) rb[p] = bpred[p] ? *(const float4*)(pb + (size_t)(32*p) * K + koff) : z4;
                else        rb[p] = *(const float4*)(pb + ((size_t)(8*p) + (size_t)koff) * N);
            }
        }

        #pragma unroll
        for (int ks = 0; ks < 2; ks++) {
            uint32_t ah[2][4], al[2][4], bh[8][2], bl[8][2];
            #pragma unroll
            for (int mt = 0; mt < 2; mt++) {
                uint32_t addr = sbase + (uint32_t)(wm*32 + mt*16 + (lane & 15)) * 80u
                              + (uint32_t)(ks*32) + ((lane >> 4) << 4);
                ldsm_x4(ah[mt][0], ah[mt][1], ah[mt][2], ah[mt][3], addr);
                ldsm_x4(al[mt][0], al[mt][1], al[mt][2], al[mt][3], addr + SA_LO);
            }
            #pragma unroll
            for (int ntp = 0; ntp < 4; ntp++) {
                uint32_t r0, r1, r2, r3;
                if (TRANSB) {
                    uint32_t addr = sbase + SB_HI
                                  + (uint32_t)(wn*64 + ntp*16 + (lane & 15)) * 80u
                                  + (uint32_t)(ks*32) + ((lane >> 4) << 4);
                    ldsm_x4(r0, r1, r2, r3, addr);
                    bh[2*ntp][0] = r0; bh[2*ntp+1][0] = r1;
                    bh[2*ntp][1] = r2; bh[2*ntp+1][1] = r3;
                    ldsm_x4(r0, r1, r2, r3, addr + BLO);
                    bl[2*ntp][0] = r0; bl[2*ntp+1][0] = r1;
                    bl[2*ntp][1] = r2; bl[2*ntp+1][1] = r3;
                } else {
                    uint32_t addr = sbase + SB_HI
                                  + (uint32_t)(ks*16 + (lane & 15)) * 272u
                                  + (uint32_t)(wn*64 + ntp*16) * 2u + ((lane >> 4) << 4);
                    ldsm_x4_t(r0, r1, r2, r3, addr);
                    bh[2*ntp][0] = r0; bh[2*ntp][1] = r1;
                    bh[2*ntp+1][0] = r2; bh[2*ntp+1][1] = r3;
                    ldsm_x4_t(r0, r1, r2, r3, addr + BLO);
                    bl[2*ntp][0] = r0; bl[2*ntp][1] = r1;
                    bl[2*ntp+1][0] = r2; bl[2*ntp+1][1] = r3;
                }
            }
            #pragma unroll
            for (int mt = 0; mt < 2; mt++)
                #pragma unroll
                for (int nt = 0; nt < 8; nt++) {
                    mma16816(acc[mt][nt], ah[mt], bh[nt]);
                    mma16816(acc[mt][nt], ah[mt], bl[nt]);
                    mma16816(acc[mt][nt], al[mt], bh[nt]);
                }
        }
        __syncthreads();
    }

    const int mrow = m0 + wm*32;
    #pragma unroll
    for (int mt = 0; mt < 2; mt++) {
        #pragma unroll
        for (int nt = 0; nt < 8; nt++) {
            int col = n0 + wn*64 + nt*8 + tig*2;
            bool ok0 = (!TRANSB) || (col < N);
            bool ok1 = (!TRANSB) || (col + 1 < N);
            float b0v = 0.f, b1v = 0.f;
            if (bias) { if (ok0) b0v = bias[col]; if (ok1) b1v = bias[col+1]; }
            #pragma unroll
            for (int hh = 0; hh < 2; hh++) {
                int row = mrow + mt*16 + grp + hh*8;
                float v0 = acc[mt][nt][2*hh+0] + b0v;
                float v1 = acc[mt][nt][2*hh+1] + b1v;
                if (act) { v0 = gelu_exact(v0); v1 = gelu_exact(v1); }
                size_t base = (size_t)row * N + col;
                if (res) { if (ok0) v0 += res[base]; if (ok1) v1 += res[base+1]; }
                if (!TRANSB) {
                    float2 o; o.x = v0; o.y = v1;
                    *(float2*)(C + base) = o;
                } else {
                    if (ok0) C[base] = v0;
                    if (ok1) C[base+1] = v1;
                }
            }
        }
    }
}

// ============ fused QKV GEMM: 3 weight mats, one launch, ldc=2304 ============
__global__ void __launch_bounds__(256, 1)
qkv_gemm(const float* __restrict__ A,
         const float* __restrict__ Wq_, const float* __restrict__ Wk_, const float* __restrict__ Wv_,
         const float* __restrict__ bq_, const float* __restrict__ bk_, const float* __restrict__ bv_,
         float* __restrict__ C)
{
    __shared__ __align__(16) unsigned char sm[SB_HI + 2*8704];
    const int BLO = 8704;
    const int K = DD, N = DD;
    const uint32_t sbase = smem_u32(sm);
    const int tid = threadIdx.x, lane = tid & 31, wid = tid >> 5;
    const int wm = wid & 3, wn = wid >> 2;
    const int m0 = blockIdx.y << 7;
    const int sel = blockIdx.x / 6;
    const int n0 = (blockIdx.x % 6) << 7;
    const float* Bw   = (sel == 0) ? Wq_ : (sel == 1) ? Wk_ : Wv_;
    const float* bias = (sel == 0) ? bq_ : (sel == 1) ? bk_ : bv_;
    const int grp = lane >> 2, tig = lane & 3;

    float acc[2][8][4];
    #pragma unroll
    for (int i = 0; i < 2; i++)
        #pragma unroll
        for (int j = 0; j < 8; j++)
            #pragma unroll
            for (int q = 0; q < 4; q++) acc[i][j][q] = 0.f;

    const int arow = tid >> 3, ak4 = tid & 7;
    const float* pa = A + (size_t)(m0 + arow) * K + ak4 * 4;
    const float* pb = Bw + (size_t)(tid >> 5) * N + n0 + (tid & 31) * 4;

    const int NC = K >> 5;
    float4 ra[4], rb[4];
    #pragma unroll
    for (int p = 0; p < 4; p++) {
        ra[p] = *(const float4*)(pa + (size_t)(32*p) * K);
        rb[p] = *(const float4*)(pb + (size_t)(8*p) * N);
    }

    for (int kc = 0; kc < NC; kc++) {
        #pragma unroll
        for (int p = 0; p < 4; p++) {
            uint2 hi, lo;
            split4(ra[p], hi, lo);
            uint32_t aoff = (uint32_t)(arow + 32*p) * 80u + (uint32_t)ak4 * 8u;
            *(uint2*)(sm + aoff)         = hi;
            *(uint2*)(sm + SA_LO + aoff) = lo;
            split4(rb[p], hi, lo);
            uint32_t boff = (uint32_t)((tid >> 5) + 8*p) * 272u + (uint32_t)(tid & 31) * 8u;
            *(uint2*)(sm + SB_HI + boff)       = hi;
            *(uint2*)(sm + SB_HI + BLO + boff) = lo;
        }
        __syncthreads();

        if (kc + 1 < NC) {
            const int koff = (kc + 1) * 32;
            #pragma unroll
            for (int p = 0; p < 4; p++) {
                ra[p] = *(const float4*)(pa + (size_t)(32*p) * K + koff);
                rb[p] = *(const float4*)(pb + ((size_t)(8*p) + (size_t)koff) * N);
            }
        }

        #pragma unroll
        for (int ks = 0; ks < 2; ks++) {
            uint32_t ah[2][4], al[2][4], bh[8][2], bl[8][2];
            #pragma unroll
            for (int mt = 0; mt < 2; mt++) {
                uint32_t addr = sbase + (uint32_t)(wm*32 + mt*16 + (lane & 15)) * 80u
                              + (uint32_t)(ks*32) + ((lane >> 4) << 4);
                ldsm_x4(ah[mt][0], ah[mt][1], ah[mt][2], ah[mt][3], addr);
                ldsm_x4(al[mt][0], al[mt][1], al[mt][2], al[mt][3], addr + SA_LO);
            }
            #pragma unroll
            for (int ntp = 0; ntp < 4; ntp++) {
                uint32_t r0, r1, r2, r3;
                uint32_t addr = sbase + SB_HI
                              + (uint32_t)(ks*16 + (lane & 15)) * 272u
                              + (uint32_t)(wn*64 + ntp*16) * 2u + ((lane >> 4) << 4);
                ldsm_x4_t(r0, r1, r2, r3, addr);
                bh[2*ntp][0] = r0; bh[2*ntp][1] = r1;
                bh[2*ntp+1][0] = r2; bh[2*ntp+1][1] = r3;
                ldsm_x4_t(r0, r1, r2, r3, addr + BLO);
                bl[2*ntp][0] = r0; bl[2*ntp][1] = r1;
                bl[2*ntp+1][0] = r2; bl[2*ntp+1][1] = r3;
            }
            #pragma unroll
            for (int mt = 0; mt < 2; mt++)
                #pragma unroll
                for (int nt = 0; nt < 8; nt++) {
                    mma16816(acc[mt][nt], ah[mt], bh[nt]);
                    mma16816(acc[mt][nt], ah[mt], bl[nt]);
                    mma16816(acc[mt][nt], al[mt], bh[nt]);
                }
        }
        __syncthreads();
    }

    const int mrow = m0 + wm*32;
    #pragma unroll
    for (int mt = 0; mt < 2; mt++) {
        #pragma unroll
        for (int nt = 0; nt < 8; nt++) {
            int col = n0 + wn*64 + nt*8 + tig*2;   // within 768
            float b0v = bias[col], b1v = bias[col+1];
            #pragma unroll
            for (int hh = 0; hh < 2; hh++) {
                int row = mrow + mt*16 + grp + hh*8;
                float v0 = acc[mt][nt][2*hh+0] + b0v;
                float v1 = acc[mt][nt][2*hh+1] + b1v;
                float2 o; o.x = v0; o.y = v1;
                *(float2*)(C + (size_t)row * (3*DD) + sel*DD + col) = o;
            }
        }
    }
}

// ============ flash attention (split-bf16 MMA, online softmax) ============
// grid (16 qtiles, 24 bh), 128 threads. qkv: (M, 2304) packed q|k|v.
__global__ void __launch_bounds__(128, 1)
flash_kernel(const float* __restrict__ qkv, const float* __restrict__ amask,
             float* __restrict__ out)
{
    __shared__ __align__(16) unsigned char sm[4*9216 + 256];
    const int KHo = 0, KLo = 9216, VHo = 18432, VLo = 27648, AMo = 36864;
    const uint32_t sbase = smem_u32(sm);
    const int tid = threadIdx.x, lane = tid & 31, w = tid >> 5;
    const int grp = lane >> 2, tig = lane & 3;
    const int qt = (int)gridDim.x - 1 - (int)blockIdx.x;   // big tiles first
    const int bh = blockIdx.y, b = bh / HH, h = bh % HH;
    const int q0 = qt * 64;

    // Q fragments direct from global, hoisted
    uint32_t qh[4][4], ql[4][4];
    #pragma unroll
    for (int ks = 0; ks < 4; ks++)
        #pragma unroll
        for (int j = 0; j < 4; j++) {
            int row = q0 + w*16 + grp + (j & 1) * 8;
            int col = h*64 + ks*16 + (j >> 1) * 8 + tig*2;
            float2 qv = *(const float2*)(qkv + (size_t)(b*SS + row) * (3*DD) + col);
            split2(qv.x, qv.y, qh[ks][j], ql[ks][j]);
        }

    float o[8][4];
    #pragma unroll
    for (int i = 0; i < 8; i++)
        #pragma unroll
        for (int j = 0; j < 4; j++) o[i][j] = 0.f;
    float mrow0 = -1e30f, mrow1 = -1e30f, lrow0 = 0.f, lrow1 = 0.f;
    const int qr0 = q0 + w*16 + grp, qr1 = qr0 + 8;

    for (int kt = 0; kt <= qt; kt++) {
        __syncthreads();
        const size_t kbase = (size_t)(b*SS + kt*64) * (3*DD) + DD + h*64;
        for (int idx = tid; idx < 64*16; idx += 128) {
            int r = idx >> 4, c4 = idx & 15;
            float4 kv4 = *(const float4*)(qkv + kbase + (size_t)r*(3*DD) + c4*4);
            uint2 hi, lo; split4(kv4, hi, lo);
            *(uint2*)(sm + KHo + r*144 + c4*8) = hi;
            *(uint2*)(sm + KLo + r*144 + c4*8) = lo;
            float4 vv4 = *(const float4*)(qkv + kbase + DD + (size_t)r*(3*DD) + c4*4);
            split4(vv4, hi, lo);
            *(uint2*)(sm + VHo + r*144 + c4*8) = hi;
            *(uint2*)(sm + VLo + r*144 + c4*8) = lo;
        }
        if (tid < 64) ((float*)(sm + AMo))[tid] = amask[b*SS + kt*64 + tid];
        __syncthreads();

        // ---- S = Q K^T ----
        float s[8][4];
        #pragma unroll
        for (int i = 0; i < 8; i++)
            #pragma unroll
            for (int j = 0; j < 4; j++) s[i][j] = 0.f;
        #pragma unroll
        for (int ks = 0; ks < 4; ks++) {
            uint32_t kh_[8][2], kl_[8][2];
            #pragma unroll
            for (int ntp = 0; ntp < 4; ntp++) {
                uint32_t r0, r1, r2, r3;
                uint32_t addr = sbase + KHo + (uint32_t)(ntp*16 + (lane & 15)) * 144u
                              + (uint32_t)(ks*32) + ((lane >> 4) << 4);
                ldsm_x4(r0, r1, r2, r3, addr);
                kh_[2*ntp][0] = r0; kh_[2*ntp][1] = r2;
                kh_[2*ntp+1][0] = r1; kh_[2*ntp+1][1] = r3;
                ldsm_x4(r0, r1, r2, r3, addr + (KLo - KHo));
                kl_[2*ntp][0] = r0; kl_[2*ntp][1] = r2;
                kl_[2*ntp+1][0] = r1; kl_[2*ntp+1][1] = r3;
            }
            #pragma unroll
            for (int nt = 0; nt < 8; nt++) {
                mma16816(s[nt], qh[ks], kh_[nt]);
                mma16816(s[nt], qh[ks], kl_[nt]);
                mma16816(s[nt], ql[ks], kh_[nt]);
            }
        }
        // ---- mask + scale ----
        const float* am = (const float*)(sm + AMo);
        #pragma unroll
        for (int nt = 0; nt < 8; nt++) {
            int c0 = nt*8 + tig*2;
            int kc0 = kt*64 + c0, kc1 = kc0 + 1;
            float a0 = am[c0], a1 = am[c0+1];
            s[nt][0] = (kc0 <= qr0 && a0 != 0.f) ? s[nt][0]*0.125f : -1e30f;
            s[nt][1] = (kc1 <= qr0 && a1 != 0.f) ? s[nt][1]*0.125f : -1e30f;
            s[nt][2] = (kc0 <= qr1 && a0 != 0.f) ? s[nt][2]*0.125f : -1e30f;
            s[nt][3] = (kc1 <= qr1 && a1 != 0.f) ? s[nt][3]*0.125f : -1e30f;
        }
        // ---- online softmax ----
        float mx0 = -1e30f, mx1 = -1e30f;
        #pragma unroll
        for (int nt = 0; nt < 8; nt++) {
            mx0 = fmaxf(mx0, fmaxf(s[nt][0], s[nt][1]));
            mx1 = fmaxf(mx1, fmaxf(s[nt][2], s[nt][3]));
        }
        mx0 = fmaxf(mx0, __shfl_xor_sync(0xffffffffu, mx0, 1));
        mx0 = fmaxf(mx0, __shfl_xor_sync(0xffffffffu, mx0, 2));
        mx1 = fmaxf(mx1, __shfl_xor_sync(0xffffffffu, mx1, 1));
        mx1 = fmaxf(mx1, __shfl_xor_sync(0xffffffffu, mx1, 2));
        float mn0 = fmaxf(mrow0, mx0), mn1 = fmaxf(mrow1, mx1);
        float sc0 = __expf(mrow0 - mn0), sc1 = __expf(mrow1 - mn1);
        mrow0 = mn0; mrow1 = mn1;
        float rs0 = 0.f, rs1 = 0.f;
        #pragma unroll
        for (int nt = 0; nt < 8; nt++) {
            s[nt][0] = __expf(s[nt][0] - mn0); rs0 += s[nt][0];
            s[nt][1] = __expf(s[nt][1] - mn0); rs0 += s[nt][1];
            s[nt][2] = __expf(s[nt][2] - mn1); rs1 += s[nt][2];
            s[nt][3] = __expf(s[nt][3] - mn1); rs1 += s[nt][3];
        }
        rs0 += __shfl_xor_sync(0xffffffffu, rs0, 1);
        rs0 += __shfl_xor_sync(0xffffffffu, rs0, 2);
        rs1 += __shfl_xor_sync(0xffffffffu, rs1, 1);
        rs1 += __shfl_xor_sync(0xffffffffu, rs1, 2);
        lrow0 = lrow0*sc0 + rs0; lrow1 = lrow1*sc1 + rs1;
        #pragma unroll
        for (int nt = 0; nt < 8; nt++) {
            o[nt][0] *= sc0; o[nt][1] *= sc0;
            o[nt][2] *= sc1; o[nt][3] *= sc1;
        }
        // ---- O += P V ----
        #pragma unroll
        for (int ks = 0; ks < 4; ks++) {
            uint32_t pah[4], pal[4];
            split2(s[2*ks][0],   s[2*ks][1],   pah[0], pal[0]);
            split2(s[2*ks][2],   s[2*ks][3],   pah[1], pal[1]);
            split2(s[2*ks+1][0], s[2*ks+1][1], pah[2], pal[2]);
            split2(s[2*ks+1][2], s[2*ks+1][3], pah[3], pal[3]);
            uint32_t vh_[8][2], vl_[8][2];
            #pragma unroll
            for (int ntp = 0; ntp < 4; ntp++) {
                uint32_t r0, r1, r2, r3;
                uint32_t addr = sbase + VHo + (uint32_t)(ks*16 + (lane & 15)) * 144u
                              + (uint32_t)(ntp*32) + ((lane >> 4) << 4);
                ldsm_x4_t(r0, r1, r2, r3, addr);
                vh_[2*ntp][0] = r0; vh_[2*ntp][1] = r1;
                vh_[2*ntp+1][0] = r2; vh_[2*ntp+1][1] = r3;
                ldsm_x4_t(r0, r1, r2, r3, addr + (VLo - VHo));
                vl_[2*ntp][0] = r0; vl_[2*ntp][1] = r1;
                vl_[2*ntp+1][0] = r2; vl_[2*ntp+1][1] = r3;
            }
            #pragma unroll
            for (int nt = 0; nt < 8; nt++) {
                mma16816(o[nt], pah, vh_[nt]);
                mma16816(o[nt], pah, vl_[nt]);
                mma16816(o[nt], pal, vh_[nt]);
            }
        }
    }
    // ---- write O / l ----
    float inv0 = 1.f / lrow0, inv1 = 1.f / lrow1;
    #pragma unroll
    for (int nt = 0; nt < 8; nt++) {
        int col = h*64 + nt*8 + tig*2;
        float2 o0; o0.x = o[nt][0]*inv0; o0.y = o[nt][1]*inv0;
        float2 o1; o1.x = o[nt][2]*inv1; o1.y = o[nt][3]*inv1;
        *(float2*)(out + (size_t)(b*SS + qr0) * DD + col) = o0;
        *(float2*)(out + (size_t)(b*SS + qr1) * DD + col) = o1;
    }
}

// ---------------- position ids ----------------
__global__ void posids_kernel(const float* __restrict__ amask, int* __restrict__ pos) {
    int b = blockIdx.x;
    if (threadIdx.x == 0) {
        float c = 0.f;
        for (int s = 0; s < SS; s++) {
            float m = amask[b*SS + s];
            c += m;
            pos[b*SS + s] = (m == 0.f) ? 0 : (int)(c - 1.f);
        }
    }
}

// ---------------- embedding ----------------
__global__ void embed_kernel(const int* __restrict__ ids, const int* __restrict__ pos,
                             const float* __restrict__ tok, const float* __restrict__ pemb,
                             float* __restrict__ x) {
    int row = blockIdx.x;
    int id = ids[row];
    int p  = pos[row];
    int tid = threadIdx.x;
    #pragma unroll
    for (int t = 0; t < 3; t++) {
        int d = tid + t*256;
        x[(size_t)row*DD + d] = tok[(size_t)id*DD + d] + pemb[(size_t)p*DD + d];
    }
}

// ---------------- layernorm ----------------
__global__ void layernorm_kernel(const float* __restrict__ x, const float* __restrict__ g,
                                 const float* __restrict__ b, float* __restrict__ y) {
    __shared__ float red[256];
    int row = blockIdx.x;
    int tid = threadIdx.x;
    const float* xr = x + (size_t)row*DD;
    float v0 = xr[tid], v1 = xr[tid+256], v2 = xr[tid+512];
    red[tid] = v0 + v1 + v2;
    __syncthreads();
    for (int s = 128; s > 0; s >>= 1) { if (tid < s) red[tid] += red[tid+s]; __syncthreads(); }
    float mu = red[0] * (1.f/DD);
    __syncthreads();
    float d0 = v0-mu, d1 = v1-mu, d2 = v2-mu;
    red[tid] = d0*d0 + d1*d1 + d2*d2;
    __syncthreads();
    for (int s = 128; s > 0; s >>= 1) { if (tid < s) red[tid] += red[tid+s]; __syncthreads(); }
    float rstd = rsqrtf(red[0] * (1.f/DD) + 1e-5f);
    float* yr = y + (size_t)row*DD;
    yr[tid]     = d0*rstd*g[tid]     + b[tid];
    yr[tid+256] = d1*rstd*g[tid+256] + b[tid+256];
    yr[tid+512] = d2*rstd*g[tid+512] + b[tid+512];
}

// ---------------- launch ----------------
extern "C" void kernel_launch(void* const* d_in, const int* in_sizes, int n_in,
                              void* d_out, int out_size) {
    const int*   ids   = (const int*)  d_in[0];
    const float* amask = (const float*)d_in[1];
    const float* tok   = (const float*)d_in[2];
    const float* pemb  = (const float*)d_in[3];
    const float* ln1g  = (const float*)d_in[4];
    const float* ln1b  = (const float*)d_in[5];
    const float* Wq    = (const float*)d_in[6];
    const float* bq    = (const float*)d_in[7];
    const float* Wk    = (const float*)d_in[8];
    const float* bk    = (const float*)d_in[9];
    const float* Wv    = (const float*)d_in[10];
    const float* bv    = (const float*)d_in[11];
    const float* Wp    = (const float*)d_in[12];
    const float* bp    = (const float*)d_in[13];
    const float* ln2g  = (const float*)d_in[14];
    const float* ln2b  = (const float*)d_in[15];
    const float* W1    = (const float*)d_in[16];
    const float* b1    = (const float*)d_in[17];
    const float* W2    = (const float*)d_in[18];
    const float* b2    = (const float*)d_in[19];
    const float* lnfg  = (const float*)d_in[20];
    const float* lnfb  = (const float*)d_in[21];
    float* out = (float*)d_out;

    float *xp, *hp, *qkvp, *ap, *fp; int* pidp;
    cudaGetSymbolAddress((void**)&xp,   g_x);
    cudaGetSymbolAddress((void**)&hp,   g_h);
    cudaGetSymbolAddress((void**)&qkvp, g_qkv);
    cudaGetSymbolAddress((void**)&ap,   g_attn);
    cudaGetSymbolAddress((void**)&fp,   g_ff);
    cudaGetSymbolAddress((void**)&pidp, g_pos);

    posids_kernel<<<BB, 32>>>(amask, pidp);
    embed_kernel<<<MM, 256>>>(ids, pidp, tok, pemb, xp);

    dim3 gD(DD/128, MM/128);           // 6 x 16
    dim3 gQKV(18, MM/128);             // 18 x 16
    dim3 gF(FF/128, MM/128);           // 24 x 16
    dim3 gV((VV+127)/128, MM/128);     // 393 x 16
    dim3 gFA(SS/64, BB*HH);            // 16 x 24

    for (int l = 0; l < LL; l++) {
        const float* wq = Wq + (size_t)l*DD*DD;  const float* bqv = bq + l*DD;
        const float* wk = Wk + (size_t)l*DD*DD;  const float* bkv = bk + l*DD;
        const float* wv = Wv + (size_t)l*DD*DD;  const float* bvv = bv + l*DD;
        const float* wp = Wp + (size_t)l*DD*DD;  const float* bpv = bp + l*DD;
        const float* w1 = W1 + (size_t)l*DD*FF;  const float* b1v = b1 + l*FF;
        const float* w2 = W2 + (size_t)l*FF*DD;  const float* b2v = b2 + l*DD;

        layernorm_kernel<<<MM, 256>>>(xp, ln1g + l*DD, ln1b + l*DD, hp);
        qkv_gemm<<<gQKV, 256>>>(hp, wq, wk, wv, bqv, bkv, bvv, qkvp);
        flash_kernel<<<gFA, 128>>>(qkvp, amask, ap);
        mma_gemm<0><<<gD, 256>>>(ap, wp, bpv, xp, xp, MM, DD, DD, 0);
        layernorm_kernel<<<MM, 256>>>(xp, ln2g + l*DD, ln2b + l*DD, hp);
        mma_gemm<0><<<gF, 256>>>(hp, w1, b1v, nullptr, fp, MM, FF, DD, 1);
        mma_gemm<0><<<gD, 256>>>(fp, w2, b2v, xp, xp, MM, DD, FF, 0);
    }

    layernorm_kernel<<<MM, 256>>>(xp, lnfg, lnfb, hp);
    mma_gemm<1><<<gV, 256>>>(hp, tok, nullptr, nullptr, out, MM, VV, DD, 0);
}

// round 7
// speedup vs baseline: 3.7643x; 1.0906x over previous
#include <cuda_runtime.h>
#include <cuda_bf16.h>
#include <math.h>
#include <stdint.h>

#define BB 2
#define SS 1024
#define DD 768
#define HH 12
#define HDD 64
#define LL 12
#define VV 50257
#define FF 3072
#define MM (BB*SS)   // 2048

// ---------------- scratch (allocation-free) ----------------
// split format: uint4 group = {hi01, hi23, lo01, lo23} for 4 consecutive elems.
__device__ float g_x[MM*DD];
__device__ int   g_pos[BB*SS];
__device__ uint4 g_h_s[MM*DD/4];
__device__ uint4 g_qkv_s[MM*3*DD/4];
__device__ uint4 g_attn_s[MM*DD/4];
__device__ uint4 g_ff_s[MM*FF/4];
__device__ uint4 g_wq_s[LL*DD*DD/4];
__device__ uint4 g_wk_s[LL*DD*DD/4];
__device__ uint4 g_wv_s[LL*DD*DD/4];
__device__ uint4 g_wp_s[LL*DD*DD/4];
__device__ uint4 g_w1_s[LL*DD*FF/4];
__device__ uint4 g_w2_s[LL*DD*FF/4];
__device__ uint4 g_tok_s[(size_t)VV*DD/4];

// ================= helpers =================
__device__ __forceinline__ uint32_t smem_u32(const void* p) {
    uint32_t a;
    asm("{ .reg .u64 t; cvta.to.shared.u64 t, %1; cvt.u32.u64 %0, t; }" : "=r"(a) : "l"(p));
    return a;
}
__device__ __forceinline__ void ldsm_x4(uint32_t& r0, uint32_t& r1, uint32_t& r2, uint32_t& r3,
                                        uint32_t addr) {
    asm volatile("ldmatrix.sync.aligned.m8n8.x4.shared.b16 {%0,%1,%2,%3}, [%4];"
                 : "=r"(r0), "=r"(r1), "=r"(r2), "=r"(r3) : "r"(addr));
}
__device__ __forceinline__ void ldsm_x4_t(uint32_t& r0, uint32_t& r1, uint32_t& r2, uint32_t& r3,
                                          uint32_t addr) {
    asm volatile("ldmatrix.sync.aligned.m8n8.x4.trans.shared.b16 {%0,%1,%2,%3}, [%4];"
                 : "=r"(r0), "=r"(r1), "=r"(r2), "=r"(r3) : "r"(addr));
}
__device__ __forceinline__ void mma16816(float* c, const uint32_t* a, const uint32_t* b) {
    asm volatile("mma.sync.aligned.m16n8k16.row.col.f32.bf16.bf16.f32 "
                 "{%0,%1,%2,%3}, {%4,%5,%6,%7}, {%8,%9}, {%0,%1,%2,%3};"
                 : "+f"(c[0]), "+f"(c[1]), "+f"(c[2]), "+f"(c[3])
                 : "r"(a[0]), "r"(a[1]), "r"(a[2]), "r"(a[3]), "r"(b[0]), "r"(b[1]));
}
__device__ __forceinline__ void split4(float4 v, uint2& hi, uint2& lo) {
    __nv_bfloat16 h0 = __float2bfloat16(v.x), h1 = __float2bfloat16(v.y);
    __nv_bfloat16 h2 = __float2bfloat16(v.z), h3 = __float2bfloat16(v.w);
    __nv_bfloat16 l0 = __float2bfloat16(v.x - __bfloat162float(h0));
    __nv_bfloat16 l1 = __float2bfloat16(v.y - __bfloat162float(h1));
    __nv_bfloat16 l2 = __float2bfloat16(v.z - __bfloat162float(h2));
    __nv_bfloat16 l3 = __float2bfloat16(v.w - __bfloat162float(h3));
    __nv_bfloat162 a = __nv_bfloat162(h0, h1), b = __nv_bfloat162(h2, h3);
    __nv_bfloat162 c = __nv_bfloat162(l0, l1), d = __nv_bfloat162(l2, l3);
    hi.x = *(uint32_t*)&a; hi.y = *(uint32_t*)&b;
    lo.x = *(uint32_t*)&c; lo.y = *(uint32_t*)&d;
}
__device__ __forceinline__ void split2(float a, float b, uint32_t& hi, uint32_t& lo) {
    __nv_bfloat16 h0 = __float2bfloat16(a), h1 = __float2bfloat16(b);
    __nv_bfloat16 l0 = __float2bfloat16(a - __bfloat162float(h0));
    __nv_bfloat16 l1 = __float2bfloat16(b - __bfloat162float(h1));
    __nv_bfloat162 H(h0, h1), L(l0, l1);
    hi = *(uint32_t*)&H; lo = *(uint32_t*)&L;
}
__device__ __forceinline__ float gelu_exact(float v) {
    return 0.5f * v * (1.0f + erff(v * 0.70710678118654752f));
}

// ---------------- fp32 -> split converter (grid-stride) ----------------
__global__ void split_kernel(const float4* __restrict__ src, uint4* __restrict__ dst, int n) {
    for (int i = blockIdx.x*blockDim.x + threadIdx.x; i < n; i += gridDim.x*blockDim.x) {
        uint2 hi, lo;
        split4(src[i], hi, lo);
        dst[i] = make_uint4(hi.x, hi.y, lo.x, lo.y);
    }
}

// ============ split-bf16 GEMM, pre-split inputs ============
// As: (M,K) split. Bs: TRANSB=0 (K,N) split; TRANSB=1 (N,K) split.
// OUTSPLIT=0: C fp32 (+bias/gelu/res). OUTSPLIT=1: Cs split (+bias/gelu).
#define SA_LO 10240
#define SB_HI 20480

template<int TRANSB, int OUTSPLIT>
__global__ void __launch_bounds__(256, 1)
mma_gemm(const uint4* __restrict__ As, const uint4* __restrict__ Bs,
         const float* __restrict__ bias, const float* __restrict__ res,
         float* __restrict__ C, uint4* __restrict__ Cs,
         int M, int N, int K, int act)
{
    __shared__ __align__(16) unsigned char sm[SB_HI + 2*10240];
    constexpr int BLO = TRANSB ? 10240 : 8704;
    const uint32_t sbase = smem_u32(sm);
    const int tid = threadIdx.x, lane = tid & 31, wid = tid >> 5;
    const int wm = wid & 3, wn = wid >> 2;
    const int m0 = blockIdx.y << 7, n0 = blockIdx.x << 7;
    const int grp = lane >> 2, tig = lane & 3;
    const int K4 = K >> 2, N4 = N >> 2;

    float acc[2][8][4];
    #pragma unroll
    for (int i = 0; i < 2; i++)
        #pragma unroll
        for (int j = 0; j < 8; j++)
            #pragma unroll
            for (int q = 0; q < 4; q++) acc[i][j][q] = 0.f;

    const int arow = tid >> 3, ak4 = tid & 7;
    const uint4* pa = As + (size_t)(m0 + arow) * K4 + ak4;

    const uint4* pb;
    bool bpred[4];
    if (TRANSB) {
        #pragma unroll
        for (int p = 0; p < 4; p++) bpred[p] = (n0 + arow + 32*p) < N;
        pb = Bs + (size_t)(n0 + arow) * K4 + ak4;
    } else {
        #pragma unroll
        for (int p = 0; p < 4; p++) bpred[p] = true;
        pb = Bs + (size_t)(tid >> 5) * N4 + (n0 >> 2) + (tid & 31);
    }

    const int NC = K >> 5;
    uint4 ra[4], rb[4];
    const uint4 z4 = make_uint4(0u, 0u, 0u, 0u);

    #pragma unroll
    for (int p = 0; p < 4; p++) {
        ra[p] = pa[(size_t)(32*p) * K4];
        if (TRANSB) rb[p] = bpred[p] ? pb[(size_t)(32*p) * K4] : z4;
        else        rb[p] = pb[(size_t)(8*p) * N4];
    }

    for (int kc = 0; kc < NC; kc++) {
        #pragma unroll
        for (int p = 0; p < 4; p++) {
            uint32_t aoff = (uint32_t)(arow + 32*p) * 80u + (uint32_t)ak4 * 8u;
            *(uint2*)(sm + aoff)         = make_uint2(ra[p].x, ra[p].y);
            *(uint2*)(sm + SA_LO + aoff) = make_uint2(ra[p].z, ra[p].w);
            uint32_t boff;
            if (TRANSB) boff = (uint32_t)(arow + 32*p) * 80u + (uint32_t)ak4 * 8u;
            else        boff = (uint32_t)((tid >> 5) + 8*p) * 272u + (uint32_t)(tid & 31) * 8u;
            *(uint2*)(sm + SB_HI + boff)       = make_uint2(rb[p].x, rb[p].y);
            *(uint2*)(sm + SB_HI + BLO + boff) = make_uint2(rb[p].z, rb[p].w);
        }
        __syncthreads();

        if (kc + 1 < NC) {
            const int kg = (kc + 1) * 8;
            #pragma unroll
            for (int p = 0; p < 4; p++) {
                ra[p] = pa[(size_t)(32*p) * K4 + kg];
                if (TRANSB) rb[p] = bpred[p] ? pb[(size_t)(32*p) * K4 + kg] : z4;
                else        rb[p] = pb[((size_t)(8*p) + (size_t)(kc+1)*32) * N4];
            }
        }

        #pragma unroll
        for (int ks = 0; ks < 2; ks++) {
            uint32_t ah[2][4], al[2][4], bh[8][2], bl[8][2];
            #pragma unroll
            for (int mt = 0; mt < 2; mt++) {
                uint32_t addr = sbase + (uint32_t)(wm*32 + mt*16 + (lane & 15)) * 80u
                              + (uint32_t)(ks*32) + ((lane >> 4) << 4);
                ldsm_x4(ah[mt][0], ah[mt][1], ah[mt][2], ah[mt][3], addr);
                ldsm_x4(al[mt][0], al[mt][1], al[mt][2], al[mt][3], addr + SA_LO);
            }
            #pragma unroll
            for (int ntp = 0; ntp < 4; ntp++) {
                uint32_t r0, r1, r2, r3;
                if (TRANSB) {
                    uint32_t addr = sbase + SB_HI
                                  + (uint32_t)(wn*64 + ntp*16 + (lane & 15)) * 80u
                                  + (uint32_t)(ks*32) + ((lane >> 4) << 4);
                    ldsm_x4(r0, r1, r2, r3, addr);
                    bh[2*ntp][0] = r0; bh[2*ntp+1][0] = r1;
                    bh[2*ntp][1] = r2; bh[2*ntp+1][1] = r3;
                    ldsm_x4(r0, r1, r2, r3, addr + BLO);
                    bl[2*ntp][0] = r0; bl[2*ntp+1][0] = r1;
                    bl[2*ntp][1] = r2; bl[2*ntp+1][1] = r3;
                } else {
                    uint32_t addr = sbase + SB_HI
                                  + (uint32_t)(ks*16 + (lane & 15)) * 272u
                                  + (uint32_t)(wn*64 + ntp*16) * 2u + ((lane >> 4) << 4);
                    ldsm_x4_t(r0, r1, r2, r3, addr);
                    bh[2*ntp][0] = r0; bh[2*ntp][1] = r1;
                    bh[2*ntp+1][0] = r2; bh[2*ntp+1][1] = r3;
                    ldsm_x4_t(r0, r1, r2, r3, addr + BLO);
                    bl[2*ntp][0] = r0; bl[2*ntp][1] = r1;
                    bl[2*ntp+1][0] = r2; bl[2*ntp+1][1] = r3;
                }
            }
            #pragma unroll
            for (int mt = 0; mt < 2; mt++)
                #pragma unroll
                for (int nt = 0; nt < 8; nt++) {
                    mma16816(acc[mt][nt], ah[mt], bh[nt]);
                    mma16816(acc[mt][nt], ah[mt], bl[nt]);
                    mma16816(acc[mt][nt], al[mt], bh[nt]);
                }
        }
        __syncthreads();
    }

    const int mrow = m0 + wm*32;
    #pragma unroll
    for (int mt = 0; mt < 2; mt++) {
        #pragma unroll
        for (int nt = 0; nt < 8; nt++) {
            int col = n0 + wn*64 + nt*8 + tig*2;
            bool ok0 = (!TRANSB) || (col < N);
            bool ok1 = (!TRANSB) || (col + 1 < N);
            float b0v = 0.f, b1v = 0.f;
            if (bias) { if (ok0) b0v = bias[col]; if (ok1) b1v = bias[col+1]; }
            #pragma unroll
            for (int hh = 0; hh < 2; hh++) {
                int row = mrow + mt*16 + grp + hh*8;
                float v0 = acc[mt][nt][2*hh+0] + b0v;
                float v1 = acc[mt][nt][2*hh+1] + b1v;
                if (act) { v0 = gelu_exact(v0); v1 = gelu_exact(v1); }
                if (OUTSPLIT) {
                    float x2 = __shfl_down_sync(0xffffffffu, v0, 1);
                    float x3 = __shfl_down_sync(0xffffffffu, v1, 1);
                    if ((tig & 1) == 0) {
                        uint2 hi, lo;
                        split4(make_float4(v0, v1, x2, x3), hi, lo);
                        Cs[(size_t)row * (N >> 2) + (col >> 2)] = make_uint4(hi.x, hi.y, lo.x, lo.y);
                    }
                } else {
                    size_t base = (size_t)row * N + col;
                    if (res) { if (ok0) v0 += res[base]; if (ok1) v1 += res[base+1]; }
                    if (!TRANSB) {
                        float2 o; o.x = v0; o.y = v1;
                        *(float2*)(C + base) = o;
                    } else {
                        if (ok0) C[base] = v0;
                        if (ok1) C[base+1] = v1;
                    }
                }
            }
        }
    }
}

// ============ fused QKV GEMM: split in, split out (M, 2304) ============
__global__ void __launch_bounds__(256, 1)
qkv_gemm(const uint4* __restrict__ As,
         const uint4* __restrict__ Wqs, const uint4* __restrict__ Wks, const uint4* __restrict__ Wvs,
         const float* __restrict__ bq_, const float* __restrict__ bk_, const float* __restrict__ bv_,
         uint4* __restrict__ Cs)
{
    __shared__ __align__(16) unsigned char sm[SB_HI + 2*8704];
    const int BLO = 8704;
    const int K4 = DD >> 2, N4 = DD >> 2;
    const uint32_t sbase = smem_u32(sm);
    const int tid = threadIdx.x, lane = tid & 31, wid = tid >> 5;
    const int wm = wid & 3, wn = wid >> 2;
    const int m0 = blockIdx.y << 7;
    const int sel = blockIdx.x / 6;
    const int n0 = (blockIdx.x % 6) << 7;
    const uint4* Bs   = (sel == 0) ? Wqs : (sel == 1) ? Wks : Wvs;
    const float* bias = (sel == 0) ? bq_ : (sel == 1) ? bk_ : bv_;
    const int grp = lane >> 2, tig = lane & 3;

    float acc[2][8][4];
    #pragma unroll
    for (int i = 0; i < 2; i++)
        #pragma unroll
        for (int j = 0; j < 8; j++)
            #pragma unroll
            for (int q = 0; q < 4; q++) acc[i][j][q] = 0.f;

    const int arow = tid >> 3, ak4 = tid & 7;
    const uint4* pa = As + (size_t)(m0 + arow) * K4 + ak4;
    const uint4* pb = Bs + (size_t)(tid >> 5) * N4 + (n0 >> 2) + (tid & 31);

    const int NC = DD >> 5;
    uint4 ra[4], rb[4];
    #pragma unroll
    for (int p = 0; p < 4; p++) {
        ra[p] = pa[(size_t)(32*p) * K4];
        rb[p] = pb[(size_t)(8*p) * N4];
    }

    for (int kc = 0; kc < NC; kc++) {
        #pragma unroll
        for (int p = 0; p < 4; p++) {
            uint32_t aoff = (uint32_t)(arow + 32*p) * 80u + (uint32_t)ak4 * 8u;
            *(uint2*)(sm + aoff)         = make_uint2(ra[p].x, ra[p].y);
            *(uint2*)(sm + SA_LO + aoff) = make_uint2(ra[p].z, ra[p].w);
            uint32_t boff = (uint32_t)((tid >> 5) + 8*p) * 272u + (uint32_t)(tid & 31) * 8u;
            *(uint2*)(sm + SB_HI + boff)       = make_uint2(rb[p].x, rb[p].y);
            *(uint2*)(sm + SB_HI + BLO + boff) = make_uint2(rb[p].z, rb[p].w);
        }
        __syncthreads();

        if (kc + 1 < NC) {
            const int kg = (kc + 1) * 8;
            #pragma unroll
            for (int p = 0; p < 4; p++) {
                ra[p] = pa[(size_t)(32*p) * K4 + kg];
                rb[p] = pb[((size_t)(8*p) + (size_t)(kc+1)*32) * N4];
            }
        }

        #pragma unroll
        for (int ks = 0; ks < 2; ks++) {
            uint32_t ah[2][4], al[2][4], bh[8][2], bl[8][2];
            #pragma unroll
            for (int mt = 0; mt < 2; mt++) {
                uint32_t addr = sbase + (uint32_t)(wm*32 + mt*16 + (lane & 15)) * 80u
                              + (uint32_t)(ks*32) + ((lane >> 4) << 4);
                ldsm_x4(ah[mt][0], ah[mt][1], ah[mt][2], ah[mt][3], addr);
                ldsm_x4(al[mt][0], al[mt][1], al[mt][2], al[mt][3], addr + SA_LO);
            }
            #pragma unroll
            for (int ntp = 0; ntp < 4; ntp++) {
                uint32_t r0, r1, r2, r3;
                uint32_t addr = sbase + SB_HI
                              + (uint32_t)(ks*16 + (lane & 15)) * 272u
                              + (uint32_t)(wn*64 + ntp*16) * 2u + ((lane >> 4) << 4);
                ldsm_x4_t(r0, r1, r2, r3, addr);
                bh[2*ntp][0] = r0; bh[2*ntp][1] = r1;
                bh[2*ntp+1][0] = r2; bh[2*ntp+1][1] = r3;
                ldsm_x4_t(r0, r1, r2, r3, addr + BLO);
                bl[2*ntp][0] = r0; bl[2*ntp][1] = r1;
                bl[2*ntp+1][0] = r2; bl[2*ntp+1][1] = r3;
            }
            #pragma unroll
            for (int mt = 0; mt < 2; mt++)
                #pragma unroll
                for (int nt = 0; nt < 8; nt++) {
                    mma16816(acc[mt][nt], ah[mt], bh[nt]);
                    mma16816(acc[mt][nt], ah[mt], bl[nt]);
                    mma16816(acc[mt][nt], al[mt], bh[nt]);
                }
        }
        __syncthreads();
    }

    const int mrow = m0 + wm*32;
    #pragma unroll
    for (int mt = 0; mt < 2; mt++) {
        #pragma unroll
        for (int nt = 0; nt < 8; nt++) {
            int col = n0 + wn*64 + nt*8 + tig*2;
            float b0v = bias[col], b1v = bias[col+1];
            #pragma unroll
            for (int hh = 0; hh < 2; hh++) {
                int row = mrow + mt*16 + grp + hh*8;
                float v0 = acc[mt][nt][2*hh+0] + b0v;
                float v1 = acc[mt][nt][2*hh+1] + b1v;
                float x2 = __shfl_down_sync(0xffffffffu, v0, 1);
                float x3 = __shfl_down_sync(0xffffffffu, v1, 1);
                if ((tig & 1) == 0) {
                    uint2 hi, lo;
                    split4(make_float4(v0, v1, x2, x3), hi, lo);
                    Cs[(size_t)row * 576 + (size_t)(sel*192) + (col >> 2)]
                        = make_uint4(hi.x, hi.y, lo.x, lo.y);
                }
            }
        }
    }
}

// ============ flash attention (split qkv input, split attn output) ============
__global__ void __launch_bounds__(128, 1)
flash_kernel(const uint4* __restrict__ qkvs, const float* __restrict__ amask,
             uint4* __restrict__ outs)
{
    __shared__ __align__(16) unsigned char sm[4*9216 + 256];
    const int KHo = 0, KLo = 9216, VHo = 18432, VLo = 27648, AMo = 36864;
    const uint32_t sbase = smem_u32(sm);
    const int tid = threadIdx.x, lane = tid & 31, w = tid >> 5;
    const int grp = lane >> 2, tig = lane & 3;
    const int qt = (int)gridDim.x - 1 - (int)blockIdx.x;
    const int bh = blockIdx.y, b = bh / HH, h = bh % HH;
    const int q0 = qt * 64;

    // Q fragments from split qkv
    uint32_t qh[4][4], ql[4][4];
    #pragma unroll
    for (int ks = 0; ks < 4; ks++)
        #pragma unroll
        for (int j = 0; j < 4; j++) {
            int row = q0 + w*16 + grp + (j & 1) * 8;
            int col = h*64 + ks*16 + (j >> 1) * 8 + tig*2;
            uint4 g = qkvs[(size_t)(b*SS + row) * 576 + (col >> 2)];
            if ((col & 3) == 0) { qh[ks][j] = g.x; ql[ks][j] = g.z; }
            else                { qh[ks][j] = g.y; ql[ks][j] = g.w; }
        }

    float o[8][4];
    #pragma unroll
    for (int i = 0; i < 8; i++)
        #pragma unroll
        for (int j = 0; j < 4; j++) o[i][j] = 0.f;
    float mrow0 = -1e30f, mrow1 = -1e30f, lrow0 = 0.f, lrow1 = 0.f;
    const int qr0 = q0 + w*16 + grp, qr1 = qr0 + 8;

    for (int kt = 0; kt <= qt; kt++) {
        __syncthreads();
        const size_t kgbase = (size_t)(b*SS + kt*64) * 576 + 192 + h*16;
        for (int idx = tid; idx < 64*16; idx += 128) {
            int r = idx >> 4, c4 = idx & 15;
            uint4 kg = qkvs[kgbase + (size_t)r*576 + c4];
            *(uint2*)(sm + KHo + r*144 + c4*8) = make_uint2(kg.x, kg.y);
            *(uint2*)(sm + KLo + r*144 + c4*8) = make_uint2(kg.z, kg.w);
            uint4 vg = qkvs[kgbase + 192 + (size_t)r*576 + c4];
            *(uint2*)(sm + VHo + r*144 + c4*8) = make_uint2(vg.x, vg.y);
            *(uint2*)(sm + VLo + r*144 + c4*8) = make_uint2(vg.z, vg.w);
        }
        if (tid < 64) ((float*)(sm + AMo))[tid] = amask[b*SS + kt*64 + tid];
        __syncthreads();

        float s[8][4];
        #pragma unroll
        for (int i = 0; i < 8; i++)
            #pragma unroll
            for (int j = 0; j < 4; j++) s[i][j] = 0.f;
        #pragma unroll
        for (int ks = 0; ks < 4; ks++) {
            uint32_t kh_[8][2], kl_[8][2];
            #pragma unroll
            for (int ntp = 0; ntp < 4; ntp++) {
                uint32_t r0, r1, r2, r3;
                uint32_t addr = sbase + KHo + (uint32_t)(ntp*16 + (lane & 15)) * 144u
                              + (uint32_t)(ks*32) + ((lane >> 4) << 4);
                ldsm_x4(r0, r1, r2, r3, addr);
                kh_[2*ntp][0] = r0; kh_[2*ntp][1] = r2;
                kh_[2*ntp+1][0] = r1; kh_[2*ntp+1][1] = r3;
                ldsm_x4(r0, r1, r2, r3, addr + (KLo - KHo));
                kl_[2*ntp][0] = r0; kl_[2*ntp][1] = r2;
                kl_[2*ntp+1][0] = r1; kl_[2*ntp+1][1] = r3;
            }
            #pragma unroll
            for (int nt = 0; nt < 8; nt++) {
                mma16816(s[nt], qh[ks], kh_[nt]);
                mma16816(s[nt], qh[ks], kl_[nt]);
                mma16816(s[nt], ql[ks], kh_[nt]);
            }
        }
        const float* am = (const float*)(sm + AMo);
        #pragma unroll
        for (int nt = 0; nt < 8; nt++) {
            int c0 = nt*8 + tig*2;
            int kc0 = kt*64 + c0, kc1 = kc0 + 1;
            float a0 = am[c0], a1 = am[c0+1];
            s[nt][0] = (kc0 <= qr0 && a0 != 0.f) ? s[nt][0]*0.125f : -1e30f;
            s[nt][1] = (kc1 <= qr0 && a1 != 0.f) ? s[nt][1]*0.125f : -1e30f;
            s[nt][2] = (kc0 <= qr1 && a0 != 0.f) ? s[nt][2]*0.125f : -1e30f;
            s[nt][3] = (kc1 <= qr1 && a1 != 0.f) ? s[nt][3]*0.125f : -1e30f;
        }
        float mx0 = -1e30f, mx1 = -1e30f;
        #pragma unroll
        for (int nt = 0; nt < 8; nt++) {
            mx0 = fmaxf(mx0, fmaxf(s[nt][0], s[nt][1]));
            mx1 = fmaxf(mx1, fmaxf(s[nt][2], s[nt][3]));
        }
        mx0 = fmaxf(mx0, __shfl_xor_sync(0xffffffffu, mx0, 1));
        mx0 = fmaxf(mx0, __shfl_xor_sync(0xffffffffu, mx0, 2));
        mx1 = fmaxf(mx1, __shfl_xor_sync(0xffffffffu, mx1, 1));
        mx1 = fmaxf(mx1, __shfl_xor_sync(0xffffffffu, mx1, 2));
        float mn0 = fmaxf(mrow0, mx0), mn1 = fmaxf(mrow1, mx1);
        float sc0 = __expf(mrow0 - mn0), sc1 = __expf(mrow1 - mn1);
        mrow0 = mn0; mrow1 = mn1;
        float rs0 = 0.f, rs1 = 0.f;
        #pragma unroll
        for (int nt = 0; nt < 8; nt++) {
            s[nt][0] = __expf(s[nt][0] - mn0); rs0 += s[nt][0];
            s[nt][1] = __expf(s[nt][1] - mn0); rs0 += s[nt][1];
            s[nt][2] = __expf(s[nt][2] - mn1); rs1 += s[nt][2];
            s[nt][3] = __expf(s[nt][3] - mn1); rs1 += s[nt][3];
        }
        rs0 += __shfl_xor_sync(0xffffffffu, rs0, 1);
        rs0 += __shfl_xor_sync(0xffffffffu, rs0, 2);
        rs1 += __shfl_xor_sync(0xffffffffu, rs1, 1);
        rs1 += __shfl_xor_sync(0xffffffffu, rs1, 2);
        lrow0 = lrow0*sc0 + rs0; lrow1 = lrow1*sc1 + rs1;
        #pragma unroll
        for (int nt = 0; nt < 8; nt++) {
            o[nt][0] *= sc0; o[nt][1] *= sc0;
            o[nt][2] *= sc1; o[nt][3] *= sc1;
        }
        #pragma unroll
        for (int ks = 0; ks < 4; ks++) {
            uint32_t pah[4], pal[4];
            split2(s[2*ks][0],   s[2*ks][1],   pah[0], pal[0]);
            split2(s[2*ks][2],   s[2*ks][3],   pah[1], pal[1]);
            split2(s[2*ks+1][0], s[2*ks+1][1], pah[2], pal[2]);
            split2(s[2*ks+1][2], s[2*ks+1][3], pah[3], pal[3]);
            uint32_t vh_[8][2], vl_[8][2];
            #pragma unroll
            for (int ntp = 0; ntp < 4; ntp++) {
                uint32_t r0, r1, r2, r3;
                uint32_t addr = sbase + VHo + (uint32_t)(ks*16 + (lane & 15)) * 144u
                              + (uint32_t)(ntp*32) + ((lane >> 4) << 4);
                ldsm_x4_t(r0, r1, r2, r3, addr);
                vh_[2*ntp][0] = r0; vh_[2*ntp][1] = r1;
                vh_[2*ntp+1][0] = r2; vh_[2*ntp+1][1] = r3;
                ldsm_x4_t(r0, r1, r2, r3, addr + (VLo - VHo));
                vl_[2*ntp][0] = r0; vl_[2*ntp][1] = r1;
                vl_[2*ntp+1][0] = r2; vl_[2*ntp+1][1] = r3;
            }
            #pragma unroll
            for (int nt = 0; nt < 8; nt++) {
                mma16816(o[nt], pah, vh_[nt]);
                mma16816(o[nt], pah, vl_[nt]);
                mma16816(o[nt], pal, vh_[nt]);
            }
        }
    }
    float inv0 = 1.f / lrow0, inv1 = 1.f / lrow1;
    #pragma unroll
    for (int nt = 0; nt < 8; nt++) {
        int col = h*64 + nt*8 + tig*2;
        float v0 = o[nt][0]*inv0, v1 = o[nt][1]*inv0;
        float u0 = o[nt][2]*inv1, u1 = o[nt][3]*inv1;
        float x2 = __shfl_down_sync(0xffffffffu, v0, 1);
        float x3 = __shfl_down_sync(0xffffffffu, v1, 1);
        float y2 = __shfl_down_sync(0xffffffffu, u0, 1);
        float y3 = __shfl_down_sync(0xffffffffu, u1, 1);
        if ((tig & 1) == 0) {
            uint2 hi, lo;
            split4(make_float4(v0, v1, x2, x3), hi, lo);
            outs[(size_t)(b*SS + qr0) * 192 + (col >> 2)] = make_uint4(hi.x, hi.y, lo.x, lo.y);
            split4(make_float4(u0, u1, y2, y3), hi, lo);
            outs[(size_t)(b*SS + qr1) * 192 + (col >> 2)] = make_uint4(hi.x, hi.y, lo.x, lo.y);
        }
    }
}

// ---------------- position ids ----------------
__global__ void posids_kernel(const float* __restrict__ amask, int* __restrict__ pos) {
    int b = blockIdx.x;
    if (threadIdx.x == 0) {
        float c = 0.f;
        for (int s = 0; s < SS; s++) {
            float m = amask[b*SS + s];
            c += m;
            pos[b*SS + s] = (m == 0.f) ? 0 : (int)(c - 1.f);
        }
    }
}

// ---------------- embedding ----------------
__global__ void embed_kernel(const int* __restrict__ ids, const int* __restrict__ pos,
                             const float* __restrict__ tok, const float* __restrict__ pemb,
                             float* __restrict__ x) {
    int row = blockIdx.x;
    int id = ids[row];
    int p  = pos[row];
    int tid = threadIdx.x;
    #pragma unroll
    for (int t = 0; t < 3; t++) {
        int d = tid + t*256;
        x[(size_t)row*DD + d] = tok[(size_t)id*DD + d] + pemb[(size_t)p*DD + d];
    }
}

// ---------------- layernorm -> split output (192 threads) ----------------
__global__ void ln_split_kernel(const float* __restrict__ x, const float* __restrict__ g,
                                const float* __restrict__ b, uint4* __restrict__ ys) {
    __shared__ float pr[6];
    int row = blockIdx.x, tid = threadIdx.x;   // 192 threads
    float4 v = ((const float4*)(x + (size_t)row*DD))[tid];
    float s = v.x + v.y + v.z + v.w;
    #pragma unroll
    for (int o = 16; o; o >>= 1) s += __shfl_xor_sync(0xffffffffu, s, o);
    if ((tid & 31) == 0) pr[tid >> 5] = s;
    __syncthreads();
    float mu = (pr[0]+pr[1]+pr[2]+pr[3]+pr[4]+pr[5]) * (1.f/DD);
    float dx = v.x-mu, dy = v.y-mu, dz = v.z-mu, dw = v.w-mu;
    float s2 = dx*dx + dy*dy + dz*dz + dw*dw;
    #pragma unroll
    for (int o = 16; o; o >>= 1) s2 += __shfl_xor_sync(0xffffffffu, s2, o);
    __syncthreads();
    if ((tid & 31) == 0) pr[tid >> 5] = s2;
    __syncthreads();
    float rstd = rsqrtf((pr[0]+pr[1]+pr[2]+pr[3]+pr[4]+pr[5]) * (1.f/DD) + 1e-5f);
    float4 gg = ((const float4*)g)[tid], bb = ((const float4*)b)[tid];
    float4 y = make_float4(dx*rstd*gg.x + bb.x, dy*rstd*gg.y + bb.y,
                           dz*rstd*gg.z + bb.z, dw*rstd*gg.w + bb.w);
    uint2 hi, lo; split4(y, hi, lo);
    ys[(size_t)row*192 + tid] = make_uint4(hi.x, hi.y, lo.x, lo.y);
}

// ---------------- launch ----------------
extern "C" void kernel_launch(void* const* d_in, const int* in_sizes, int n_in,
                              void* d_out, int out_size) {
    const int*   ids   = (const int*)  d_in[0];
    const float* amask = (const float*)d_in[1];
    const float* tok   = (const float*)d_in[2];
    const float* pemb  = (const float*)d_in[3];
    const float* ln1g  = (const float*)d_in[4];
    const float* ln1b  = (const float*)d_in[5];
    const float* Wq    = (const float*)d_in[6];
    const float* bq    = (const float*)d_in[7];
    const float* Wk    = (const float*)d_in[8];
    const float* bk    = (const float*)d_in[9];
    const float* Wv    = (const float*)d_in[10];
    const float* bv    = (const float*)d_in[11];
    const float* Wp    = (const float*)d_in[12];
    const float* bp    = (const float*)d_in[13];
    const float* ln2g  = (const float*)d_in[14];
    const float* ln2b  = (const float*)d_in[15];
    const float* W1    = (const float*)d_in[16];
    const float* b1    = (const float*)d_in[17];
    const float* W2    = (const float*)d_in[18];
    const float* b2    = (const float*)d_in[19];
    const float* lnfg  = (const float*)d_in[20];
    const float* lnfb  = (const float*)d_in[21];
    float* out = (float*)d_out;

    float *xp; int* pidp;
    uint4 *hs, *qkvs, *as, *fs, *wqs, *wks, *wvs, *wps, *w1s, *w2s, *toks;
    cudaGetSymbolAddress((void**)&xp,   g_x);
    cudaGetSymbolAddress((void**)&pidp, g_pos);
    cudaGetSymbolAddress((void**)&hs,   g_h_s);
    cudaGetSymbolAddress((void**)&qkvs, g_qkv_s);
    cudaGetSymbolAddress((void**)&as,   g_attn_s);
    cudaGetSymbolAddress((void**)&fs,   g_ff_s);
    cudaGetSymbolAddress((void**)&wqs,  g_wq_s);
    cudaGetSymbolAddress((void**)&wks,  g_wk_s);
    cudaGetSymbolAddress((void**)&wvs,  g_wv_s);
    cudaGetSymbolAddress((void**)&wps,  g_wp_s);
    cudaGetSymbolAddress((void**)&w1s,  g_w1_s);
    cudaGetSymbolAddress((void**)&w2s,  g_w2_s);
    cudaGetSymbolAddress((void**)&toks, g_tok_s);

    const int SG = 1184;  // split kernel grid
    split_kernel<<<SG, 256>>>((const float4*)Wq, wqs, LL*DD*DD/4);
    split_kernel<<<SG, 256>>>((const float4*)Wk, wks, LL*DD*DD/4);
    split_kernel<<<SG, 256>>>((const float4*)Wv, wvs, LL*DD*DD/4);
    split_kernel<<<SG, 256>>>((const float4*)Wp, wps, LL*DD*DD/4);
    split_kernel<<<SG, 256>>>((const float4*)W1, w1s, LL*DD*FF/4);
    split_kernel<<<SG, 256>>>((const float4*)W2, w2s, LL*DD*FF/4);
    split_kernel<<<SG, 256>>>((const float4*)tok, toks, VV*DD/4);

    posids_kernel<<<BB, 32>>>(amask, pidp);
    embed_kernel<<<MM, 256>>>(ids, pidp, tok, pemb, xp);

    dim3 gD(DD/128, MM/128);
    dim3 gQKV(18, MM/128);
    dim3 gF(FF/128, MM/128);
    dim3 gV((VV+127)/128, MM/128);
    dim3 gFA(SS/64, BB*HH);

    for (int l = 0; l < LL; l++) {
        const uint4* wql = wqs + (size_t)l*(DD*DD/4);
        const uint4* wkl = wks + (size_t)l*(DD*DD/4);
        const uint4* wvl = wvs + (size_t)l*(DD*DD/4);
        const uint4* wpl = wps + (size_t)l*(DD*DD/4);
        const uint4* w1l = w1s + (size_t)l*(DD*FF/4);
        const uint4* w2l = w2s + (size_t)l*(DD*FF/4);

        ln_split_kernel<<<MM, 192>>>(xp, ln1g + l*DD, ln1b + l*DD, hs);
        qkv_gemm<<<gQKV, 256>>>(hs, wql, wkl, wvl, bq + l*DD, bk + l*DD, bv + l*DD, qkvs);
        flash_kernel<<<gFA, 128>>>(qkvs, amask, as);
        mma_gemm<0,0><<<gD, 256>>>(as, wpl, bp + l*DD, xp, xp, nullptr, MM, DD, DD, 0);
        ln_split_kernel<<<MM, 192>>>(xp, ln2g + l*DD, ln2b + l*DD, hs);
        mma_gemm<0,1><<<gF, 256>>>(hs, w1l, b1 + l*FF, nullptr, nullptr, fs, MM, FF, DD, 1);
        mma_gemm<0,0><<<gD, 256>>>(fs, w2l, b2 + l*DD, xp, xp, nullptr, MM, DD, FF, 0);
    }

    ln_split_kernel<<<MM, 192>>>(xp, lnfg, lnfb, hs);
    mma_gemm<1,0><<<gV, 256>>>(hs, toks, nullptr, nullptr, out, nullptr, MM, VV, DD, 0);
}

// round 8
// speedup vs baseline: 4.0184x; 1.0675x over previous
#include <cuda_runtime.h>
#include <cuda_bf16.h>
#include <math.h>
#include <stdint.h>

#define BB 2
#define SS 1024
#define DD 768
#define HH 12
#define HDD 64
#define LL 12
#define VV 50257
#define FF 3072
#define MM (BB*SS)   // 2048

// ---------------- scratch (allocation-free) ----------------
// split format: uint4 group = {hi01, hi23, lo01, lo23} for 4 consecutive elems.
__device__ float g_x[MM*DD];
__device__ int   g_pos[BB*SS];
__device__ uint4 g_h_s[MM*DD/4];
__device__ uint4 g_qkv_s[MM*3*DD/4];
__device__ uint4 g_attn_s[MM*DD/4];
__device__ uint4 g_ff_s[MM*FF/4];
__device__ uint4 g_wq_s[LL*DD*DD/4];
__device__ uint4 g_wk_s[LL*DD*DD/4];
__device__ uint4 g_wv_s[LL*DD*DD/4];
__device__ uint4 g_wp_s[LL*DD*DD/4];
__device__ uint4 g_w1_s[LL*DD*FF/4];
__device__ uint4 g_w2_s[LL*DD*FF/4];
__device__ uint4 g_tok_s[(size_t)VV*DD/4];

// ================= helpers =================
__device__ __forceinline__ uint32_t smem_u32(const void* p) {
    uint32_t a;
    asm("{ .reg .u64 t; cvta.to.shared.u64 t, %1; cvt.u32.u64 %0, t; }" : "=r"(a) : "l"(p));
    return a;
}
__device__ __forceinline__ void ldsm_x4(uint32_t& r0, uint32_t& r1, uint32_t& r2, uint32_t& r3,
                                        uint32_t addr) {
    asm volatile("ldmatrix.sync.aligned.m8n8.x4.shared.b16 {%0,%1,%2,%3}, [%4];"
                 : "=r"(r0), "=r"(r1), "=r"(r2), "=r"(r3) : "r"(addr));
}
__device__ __forceinline__ void ldsm_x4_t(uint32_t& r0, uint32_t& r1, uint32_t& r2, uint32_t& r3,
                                          uint32_t addr) {
    asm volatile("ldmatrix.sync.aligned.m8n8.x4.trans.shared.b16 {%0,%1,%2,%3}, [%4];"
                 : "=r"(r0), "=r"(r1), "=r"(r2), "=r"(r3) : "r"(addr));
}
__device__ __forceinline__ void mma16816(float* c, const uint32_t* a, const uint32_t* b) {
    asm volatile("mma.sync.aligned.m16n8k16.row.col.f32.bf16.bf16.f32 "
                 "{%0,%1,%2,%3}, {%4,%5,%6,%7}, {%8,%9}, {%0,%1,%2,%3};"
                 : "+f"(c[0]), "+f"(c[1]), "+f"(c[2]), "+f"(c[3])
                 : "r"(a[0]), "r"(a[1]), "r"(a[2]), "r"(a[3]), "r"(b[0]), "r"(b[1]));
}
__device__ __forceinline__ void split4(float4 v, uint2& hi, uint2& lo) {
    __nv_bfloat16 h0 = __float2bfloat16(v.x), h1 = __float2bfloat16(v.y);
    __nv_bfloat16 h2 = __float2bfloat16(v.z), h3 = __float2bfloat16(v.w);
    __nv_bfloat16 l0 = __float2bfloat16(v.x - __bfloat162float(h0));
    __nv_bfloat16 l1 = __float2bfloat16(v.y - __bfloat162float(h1));
    __nv_bfloat16 l2 = __float2bfloat16(v.z - __bfloat162float(h2));
    __nv_bfloat16 l3 = __float2bfloat16(v.w - __bfloat162float(h3));
    __nv_bfloat162 a = __nv_bfloat162(h0, h1), b = __nv_bfloat162(h2, h3);
    __nv_bfloat162 c = __nv_bfloat162(l0, l1), d = __nv_bfloat162(l2, l3);
    hi.x = *(uint32_t*)&a; hi.y = *(uint32_t*)&b;
    lo.x = *(uint32_t*)&c; lo.y = *(uint32_t*)&d;
}
__device__ __forceinline__ void split2(float a, float b, uint32_t& hi, uint32_t& lo) {
    __nv_bfloat16 h0 = __float2bfloat16(a), h1 = __float2bfloat16(b);
    __nv_bfloat16 l0 = __float2bfloat16(a - __bfloat162float(h0));
    __nv_bfloat16 l1 = __float2bfloat16(b - __bfloat162float(h1));
    __nv_bfloat162 H(h0, h1), L(l0, l1);
    hi = *(uint32_t*)&H; lo = *(uint32_t*)&L;
}
__device__ __forceinline__ float gelu_exact(float v) {
    return 0.5f * v * (1.0f + erff(v * 0.70710678118654752f));
}

// ---------------- fp32 -> split converter (grid-stride) ----------------
__global__ void split_kernel(const float4* __restrict__ src, uint4* __restrict__ dst, int n) {
    for (int i = blockIdx.x*blockDim.x + threadIdx.x; i < n; i += gridDim.x*blockDim.x) {
        uint2 hi, lo;
        split4(src[i], hi, lo);
        dst[i] = make_uint4(hi.x, hi.y, lo.x, lo.y);
    }
}

// ============ split-bf16 GEMM, pre-split inputs, double-buffered smem ============
// smem per buffer: Ahi[10240] Alo[10240] Bhi[BHI] Blo[BHI]; two buffers.
template<int TRANSB, int OUTSPLIT>
__global__ void __launch_bounds__(256, 1)
mma_gemm(const uint4* __restrict__ As, const uint4* __restrict__ Bs,
         const float* __restrict__ bias, const float* __restrict__ res,
         float* __restrict__ C, uint4* __restrict__ Cs,
         int M, int N, int K, int act)
{
    extern __shared__ __align__(16) unsigned char sm[];
    constexpr int BHI   = TRANSB ? 10240 : 8704;
    constexpr int BOFF  = 20480;                 // A hi+lo
    constexpr int BUFSZ = BOFF + 2*BHI;
    const uint32_t sbase = smem_u32(sm);
    const int tid = threadIdx.x, lane = tid & 31, wid = tid >> 5;
    const int wm = wid & 3, wn = wid >> 2;
    const int m0 = blockIdx.y << 7, n0 = blockIdx.x << 7;
    const int grp = lane >> 2, tig = lane & 3;
    const int K4 = K >> 2, N4 = N >> 2;

    float acc[2][8][4];
    #pragma unroll
    for (int i = 0; i < 2; i++)
        #pragma unroll
        for (int j = 0; j < 8; j++)
            #pragma unroll
            for (int q = 0; q < 4; q++) acc[i][j][q] = 0.f;

    const int arow = tid >> 3, ak4 = tid & 7;
    const uint4* pa = As + (size_t)(m0 + arow) * K4 + ak4;

    const uint4* pb;
    bool bpred[4];
    if (TRANSB) {
        #pragma unroll
        for (int p = 0; p < 4; p++) bpred[p] = (n0 + arow + 32*p) < N;
        pb = Bs + (size_t)(n0 + arow) * K4 + ak4;
    } else {
        #pragma unroll
        for (int p = 0; p < 4; p++) bpred[p] = true;
        pb = Bs + (size_t)(tid >> 5) * N4 + (n0 >> 2) + (tid & 31);
    }

    const int NC = K >> 5;
    uint4 ra[4], rb[4];
    const uint4 z4 = make_uint4(0u, 0u, 0u, 0u);

    // smem store offsets (per-thread, buffer-relative)
    const uint32_t aoff_t = (uint32_t)arow * 80u + (uint32_t)ak4 * 8u;
    uint32_t boff_t;
    if (TRANSB) boff_t = aoff_t;
    else        boff_t = (uint32_t)(tid >> 5) * 272u + (uint32_t)(tid & 31) * 8u;

    // ---- load chunk 0 + store buffer 0 ----
    #pragma unroll
    for (int p = 0; p < 4; p++) {
        ra[p] = pa[(size_t)(32*p) * K4];
        if (TRANSB) rb[p] = bpred[p] ? pb[(size_t)(32*p) * K4] : z4;
        else        rb[p] = pb[(size_t)(8*p) * N4];
    }
    #pragma unroll
    for (int p = 0; p < 4; p++) {
        uint32_t ao = aoff_t + (uint32_t)(32*p) * 80u;
        *(uint2*)(sm + ao)         = make_uint2(ra[p].x, ra[p].y);
        *(uint2*)(sm + 10240 + ao) = make_uint2(ra[p].z, ra[p].w);
        uint32_t bo = TRANSB ? (boff_t + (uint32_t)(32*p) * 80u)
                             : (boff_t + (uint32_t)(8*p) * 272u);
        *(uint2*)(sm + BOFF + bo)       = make_uint2(rb[p].x, rb[p].y);
        *(uint2*)(sm + BOFF + BHI + bo) = make_uint2(rb[p].z, rb[p].w);
    }
    __syncthreads();

    for (int kc = 0; kc < NC; kc++) {
        // ---- prefetch next chunk into regs ----
        if (kc + 1 < NC) {
            const int kg = (kc + 1) * 8;
            #pragma unroll
            for (int p = 0; p < 4; p++) {
                ra[p] = pa[(size_t)(32*p) * K4 + kg];
                if (TRANSB) rb[p] = bpred[p] ? pb[(size_t)(32*p) * K4 + kg] : z4;
                else        rb[p] = pb[((size_t)(8*p) + (size_t)(kc+1)*32) * N4];
            }
        }

        // ---- compute from buffer kc&1 ----
        const uint32_t cb = sbase + (uint32_t)(kc & 1) * BUFSZ;
        #pragma unroll
        for (int ks = 0; ks < 2; ks++) {
            uint32_t ah[2][4], al[2][4], bh[8][2], bl[8][2];
            #pragma unroll
            for (int mt = 0; mt < 2; mt++) {
                uint32_t addr = cb + (uint32_t)(wm*32 + mt*16 + (lane & 15)) * 80u
                              + (uint32_t)(ks*32) + ((lane >> 4) << 4);
                ldsm_x4(ah[mt][0], ah[mt][1], ah[mt][2], ah[mt][3], addr);
                ldsm_x4(al[mt][0], al[mt][1], al[mt][2], al[mt][3], addr + 10240);
            }
            #pragma unroll
            for (int ntp = 0; ntp < 4; ntp++) {
                uint32_t r0, r1, r2, r3;
                if (TRANSB) {
                    uint32_t addr = cb + BOFF
                                  + (uint32_t)(wn*64 + ntp*16 + (lane & 15)) * 80u
                                  + (uint32_t)(ks*32) + ((lane >> 4) << 4);
                    ldsm_x4(r0, r1, r2, r3, addr);
                    bh[2*ntp][0] = r0; bh[2*ntp+1][0] = r1;
                    bh[2*ntp][1] = r2; bh[2*ntp+1][1] = r3;
                    ldsm_x4(r0, r1, r2, r3, addr + BHI);
                    bl[2*ntp][0] = r0; bl[2*ntp+1][0] = r1;
                    bl[2*ntp][1] = r2; bl[2*ntp+1][1] = r3;
                } else {
                    uint32_t addr = cb + BOFF
                                  + (uint32_t)(ks*16 + (lane & 15)) * 272u
                                  + (uint32_t)(wn*64 + ntp*16) * 2u + ((lane >> 4) << 4);
                    ldsm_x4_t(r0, r1, r2, r3, addr);
                    bh[2*ntp][0] = r0; bh[2*ntp][1] = r1;
                    bh[2*ntp+1][0] = r2; bh[2*ntp+1][1] = r3;
                    ldsm_x4_t(r0, r1, r2, r3, addr + BHI);
                    bl[2*ntp][0] = r0; bl[2*ntp][1] = r1;
                    bl[2*ntp+1][0] = r2; bl[2*ntp+1][1] = r3;
                }
            }
            #pragma unroll
            for (int mt = 0; mt < 2; mt++)
                #pragma unroll
                for (int nt = 0; nt < 8; nt++) {
                    mma16816(acc[mt][nt], ah[mt], bh[nt]);
                    mma16816(acc[mt][nt], ah[mt], bl[nt]);
                    mma16816(acc[mt][nt], al[mt], bh[nt]);
                }
        }

        // ---- store next chunk into buffer (kc+1)&1, one sync ----
        if (kc + 1 < NC) {
            unsigned char* nb = sm + (uint32_t)((kc + 1) & 1) * BUFSZ;
            #pragma unroll
            for (int p = 0; p < 4; p++) {
                uint32_t ao = aoff_t + (uint32_t)(32*p) * 80u;
                *(uint2*)(nb + ao)         = make_uint2(ra[p].x, ra[p].y);
                *(uint2*)(nb + 10240 + ao) = make_uint2(ra[p].z, ra[p].w);
                uint32_t bo = TRANSB ? (boff_t + (uint32_t)(32*p) * 80u)
                                     : (boff_t + (uint32_t)(8*p) * 272u);
                *(uint2*)(nb + BOFF + bo)       = make_uint2(rb[p].x, rb[p].y);
                *(uint2*)(nb + BOFF + BHI + bo) = make_uint2(rb[p].z, rb[p].w);
            }
            __syncthreads();
        }
    }

    const int mrow = m0 + wm*32;
    #pragma unroll
    for (int mt = 0; mt < 2; mt++) {
        #pragma unroll
        for (int nt = 0; nt < 8; nt++) {
            int col = n0 + wn*64 + nt*8 + tig*2;
            bool ok0 = (!TRANSB) || (col < N);
            bool ok1 = (!TRANSB) || (col + 1 < N);
            float b0v = 0.f, b1v = 0.f;
            if (bias) { if (ok0) b0v = bias[col]; if (ok1) b1v = bias[col+1]; }
            #pragma unroll
            for (int hh = 0; hh < 2; hh++) {
                int row = mrow + mt*16 + grp + hh*8;
                float v0 = acc[mt][nt][2*hh+0] + b0v;
                float v1 = acc[mt][nt][2*hh+1] + b1v;
                if (act) { v0 = gelu_exact(v0); v1 = gelu_exact(v1); }
                if (OUTSPLIT) {
                    float x2 = __shfl_down_sync(0xffffffffu, v0, 1);
                    float x3 = __shfl_down_sync(0xffffffffu, v1, 1);
                    if ((tig & 1) == 0) {
                        uint2 hi, lo;
                        split4(make_float4(v0, v1, x2, x3), hi, lo);
                        Cs[(size_t)row * (N >> 2) + (col >> 2)] = make_uint4(hi.x, hi.y, lo.x, lo.y);
                    }
                } else {
                    size_t base = (size_t)row * N + col;
                    if (res) { if (ok0) v0 += res[base]; if (ok1) v1 += res[base+1]; }
                    if (!TRANSB) {
                        float2 o; o.x = v0; o.y = v1;
                        *(float2*)(C + base) = o;
                    } else {
                        if (ok0) C[base] = v0;
                        if (ok1) C[base+1] = v1;
                    }
                }
            }
        }
    }
}

// ============ fused QKV GEMM: split in/out, double-buffered ============
__global__ void __launch_bounds__(256, 1)
qkv_gemm(const uint4* __restrict__ As,
         const uint4* __restrict__ Wqs, const uint4* __restrict__ Wks, const uint4* __restrict__ Wvs,
         const float* __restrict__ bq_, const float* __restrict__ bk_, const float* __restrict__ bv_,
         uint4* __restrict__ Cs)
{
    extern __shared__ __align__(16) unsigned char sm[];
    constexpr int BHI   = 8704;
    constexpr int BOFF  = 20480;
    constexpr int BUFSZ = BOFF + 2*BHI;   // 37888
    const int K4 = DD >> 2, N4 = DD >> 2;
    const uint32_t sbase = smem_u32(sm);
    const int tid = threadIdx.x, lane = tid & 31, wid = tid >> 5;
    const int wm = wid & 3, wn = wid >> 2;
    const int m0 = blockIdx.y << 7;
    const int sel = blockIdx.x / 6;
    const int n0 = (blockIdx.x % 6) << 7;
    const uint4* Bs   = (sel == 0) ? Wqs : (sel == 1) ? Wks : Wvs;
    const float* bias = (sel == 0) ? bq_ : (sel == 1) ? bk_ : bv_;
    const int grp = lane >> 2, tig = lane & 3;

    float acc[2][8][4];
    #pragma unroll
    for (int i = 0; i < 2; i++)
        #pragma unroll
        for (int j = 0; j < 8; j++)
            #pragma unroll
            for (int q = 0; q < 4; q++) acc[i][j][q] = 0.f;

    const int arow = tid >> 3, ak4 = tid & 7;
    const uint4* pa = As + (size_t)(m0 + arow) * K4 + ak4;
    const uint4* pb = Bs + (size_t)(tid >> 5) * N4 + (n0 >> 2) + (tid & 31);

    const int NC = DD >> 5;
    uint4 ra[4], rb[4];
    const uint32_t aoff_t = (uint32_t)arow * 80u + (uint32_t)ak4 * 8u;
    const uint32_t boff_t = (uint32_t)(tid >> 5) * 272u + (uint32_t)(tid & 31) * 8u;

    #pragma unroll
    for (int p = 0; p < 4; p++) {
        ra[p] = pa[(size_t)(32*p) * K4];
        rb[p] = pb[(size_t)(8*p) * N4];
    }
    #pragma unroll
    for (int p = 0; p < 4; p++) {
        uint32_t ao = aoff_t + (uint32_t)(32*p) * 80u;
        *(uint2*)(sm + ao)         = make_uint2(ra[p].x, ra[p].y);
        *(uint2*)(sm + 10240 + ao) = make_uint2(ra[p].z, ra[p].w);
        uint32_t bo = boff_t + (uint32_t)(8*p) * 272u;
        *(uint2*)(sm + BOFF + bo)       = make_uint2(rb[p].x, rb[p].y);
        *(uint2*)(sm + BOFF + BHI + bo) = make_uint2(rb[p].z, rb[p].w);
    }
    __syncthreads();

    for (int kc = 0; kc < NC; kc++) {
        if (kc + 1 < NC) {
            const int kg = (kc + 1) * 8;
            #pragma unroll
            for (int p = 0; p < 4; p++) {
                ra[p] = pa[(size_t)(32*p) * K4 + kg];
                rb[p] = pb[((size_t)(8*p) + (size_t)(kc+1)*32) * N4];
            }
        }

        const uint32_t cb = sbase + (uint32_t)(kc & 1) * BUFSZ;
        #pragma unroll
        for (int ks = 0; ks < 2; ks++) {
            uint32_t ah[2][4], al[2][4], bh[8][2], bl[8][2];
            #pragma unroll
            for (int mt = 0; mt < 2; mt++) {
                uint32_t addr = cb + (uint32_t)(wm*32 + mt*16 + (lane & 15)) * 80u
                              + (uint32_t)(ks*32) + ((lane >> 4) << 4);
                ldsm_x4(ah[mt][0], ah[mt][1], ah[mt][2], ah[mt][3], addr);
                ldsm_x4(al[mt][0], al[mt][1], al[mt][2], al[mt][3], addr + 10240);
            }
            #pragma unroll
            for (int ntp = 0; ntp < 4; ntp++) {
                uint32_t r0, r1, r2, r3;
                uint32_t addr = cb + BOFF
                              + (uint32_t)(ks*16 + (lane & 15)) * 272u
                              + (uint32_t)(wn*64 + ntp*16) * 2u + ((lane >> 4) << 4);
                ldsm_x4_t(r0, r1, r2, r3, addr);
                bh[2*ntp][0] = r0; bh[2*ntp][1] = r1;
                bh[2*ntp+1][0] = r2; bh[2*ntp+1][1] = r3;
                ldsm_x4_t(r0, r1, r2, r3, addr + BHI);
                bl[2*ntp][0] = r0; bl[2*ntp][1] = r1;
                bl[2*ntp+1][0] = r2; bl[2*ntp+1][1] = r3;
            }
            #pragma unroll
            for (int mt = 0; mt < 2; mt++)
                #pragma unroll
                for (int nt = 0; nt < 8; nt++) {
                    mma16816(acc[mt][nt], ah[mt], bh[nt]);
                    mma16816(acc[mt][nt], ah[mt], bl[nt]);
                    mma16816(acc[mt][nt], al[mt], bh[nt]);
                }
        }

        if (kc + 1 < NC) {
            unsigned char* nb = sm + (uint32_t)((kc + 1) & 1) * BUFSZ;
            #pragma unroll
            for (int p = 0; p < 4; p++) {
                uint32_t ao = aoff_t + (uint32_t)(32*p) * 80u;
                *(uint2*)(nb + ao)         = make_uint2(ra[p].x, ra[p].y);
                *(uint2*)(nb + 10240 + ao) = make_uint2(ra[p].z, ra[p].w);
                uint32_t bo = boff_t + (uint32_t)(8*p) * 272u;
                *(uint2*)(nb + BOFF + bo)       = make_uint2(rb[p].x, rb[p].y);
                *(uint2*)(nb + BOFF + BHI + bo) = make_uint2(rb[p].z, rb[p].w);
            }
            __syncthreads();
        }
    }

    const int mrow = m0 + wm*32;
    #pragma unroll
    for (int mt = 0; mt < 2; mt++) {
        #pragma unroll
        for (int nt = 0; nt < 8; nt++) {
            int col = n0 + wn*64 + nt*8 + tig*2;
            float b0v = bias[col], b1v = bias[col+1];
            #pragma unroll
            for (int hh = 0; hh < 2; hh++) {
                int row = mrow + mt*16 + grp + hh*8;
                float v0 = acc[mt][nt][2*hh+0] + b0v;
                float v1 = acc[mt][nt][2*hh+1] + b1v;
                float x2 = __shfl_down_sync(0xffffffffu, v0, 1);
                float x3 = __shfl_down_sync(0xffffffffu, v1, 1);
                if ((tig & 1) == 0) {
                    uint2 hi, lo;
                    split4(make_float4(v0, v1, x2, x3), hi, lo);
                    Cs[(size_t)row * 576 + (size_t)(sel*192) + (col >> 2)]
                        = make_uint4(hi.x, hi.y, lo.x, lo.y);
                }
            }
        }
    }
}

// ============ flash attention (split qkv input, split attn output) ============
__global__ void __launch_bounds__(128, 1)
flash_kernel(const uint4* __restrict__ qkvs, const float* __restrict__ amask,
             uint4* __restrict__ outs)
{
    __shared__ __align__(16) unsigned char sm[4*9216 + 256];
    const int KHo = 0, KLo = 9216, VHo = 18432, VLo = 27648, AMo = 36864;
    const uint32_t sbase = smem_u32(sm);
    const int tid = threadIdx.x, lane = tid & 31, w = tid >> 5;
    const int grp = lane >> 2, tig = lane & 3;
    const int qt = (int)gridDim.x - 1 - (int)blockIdx.x;
    const int bh = blockIdx.y, b = bh / HH, h = bh % HH;
    const int q0 = qt * 64;

    uint32_t qh[4][4], ql[4][4];
    #pragma unroll
    for (int ks = 0; ks < 4; ks++)
        #pragma unroll
        for (int j = 0; j < 4; j++) {
            int row = q0 + w*16 + grp + (j & 1) * 8;
            int col = h*64 + ks*16 + (j >> 1) * 8 + tig*2;
            uint4 g = qkvs[(size_t)(b*SS + row) * 576 + (col >> 2)];
            if ((col & 3) == 0) { qh[ks][j] = g.x; ql[ks][j] = g.z; }
            else                { qh[ks][j] = g.y; ql[ks][j] = g.w; }
        }

    float o[8][4];
    #pragma unroll
    for (int i = 0; i < 8; i++)
        #pragma unroll
        for (int j = 0; j < 4; j++) o[i][j] = 0.f;
    float mrow0 = -1e30f, mrow1 = -1e30f, lrow0 = 0.f, lrow1 = 0.f;
    const int qr0 = q0 + w*16 + grp, qr1 = qr0 + 8;

    for (int kt = 0; kt <= qt; kt++) {
        __syncthreads();
        const size_t kgbase = (size_t)(b*SS + kt*64) * 576 + 192 + h*16;
        for (int idx = tid; idx < 64*16; idx += 128) {
            int r = idx >> 4, c4 = idx & 15;
            uint4 kg = qkvs[kgbase + (size_t)r*576 + c4];
            *(uint2*)(sm + KHo + r*144 + c4*8) = make_uint2(kg.x, kg.y);
            *(uint2*)(sm + KLo + r*144 + c4*8) = make_uint2(kg.z, kg.w);
            uint4 vg = qkvs[kgbase + 192 + (size_t)r*576 + c4];
            *(uint2*)(sm + VHo + r*144 + c4*8) = make_uint2(vg.x, vg.y);
            *(uint2*)(sm + VLo + r*144 + c4*8) = make_uint2(vg.z, vg.w);
        }
        if (tid < 64) ((float*)(sm + AMo))[tid] = amask[b*SS + kt*64 + tid];
        __syncthreads();

        float s[8][4];
        #pragma unroll
        for (int i = 0; i < 8; i++)
            #pragma unroll
            for (int j = 0; j < 4; j++) s[i][j] = 0.f;
        #pragma unroll
        for (int ks = 0; ks < 4; ks++) {
            uint32_t kh_[8][2], kl_[8][2];
            #pragma unroll
            for (int ntp = 0; ntp < 4; ntp++) {
                uint32_t r0, r1, r2, r3;
                uint32_t addr = sbase + KHo + (uint32_t)(ntp*16 + (lane & 15)) * 144u
                              + (uint32_t)(ks*32) + ((lane >> 4) << 4);
                ldsm_x4(r0, r1, r2, r3, addr);
                kh_[2*ntp][0] = r0; kh_[2*ntp][1] = r2;
                kh_[2*ntp+1][0] = r1; kh_[2*ntp+1][1] = r3;
                ldsm_x4(r0, r1, r2, r3, addr + (KLo - KHo));
                kl_[2*ntp][0] = r0; kl_[2*ntp][1] = r2;
                kl_[2*ntp+1][0] = r1; kl_[2*ntp+1][1] = r3;
            }
            #pragma unroll
            for (int nt = 0; nt < 8; nt++) {
                mma16816(s[nt], qh[ks], kh_[nt]);
                mma16816(s[nt], qh[ks], kl_[nt]);
                mma16816(s[nt], ql[ks], kh_[nt]);
            }
        }
        const float* am = (const float*)(sm + AMo);
        #pragma unroll
        for (int nt = 0; nt < 8; nt++) {
            int c0 = nt*8 + tig*2;
            int kc0 = kt*64 + c0, kc1 = kc0 + 1;
            float a0 = am[c0], a1 = am[c0+1];
            s[nt][0] = (kc0 <= qr0 && a0 != 0.f) ? s[nt][0]*0.125f : -1e30f;
            s[nt][1] = (kc1 <= qr0 && a1 != 0.f) ? s[nt][1]*0.125f : -1e30f;
            s[nt][2] = (kc0 <= qr1 && a0 != 0.f) ? s[nt][2]*0.125f : -1e30f;
            s[nt][3] = (kc1 <= qr1 && a1 != 0.f) ? s[nt][3]*0.125f : -1e30f;
        }
        float mx0 = -1e30f, mx1 = -1e30f;
        #pragma unroll
        for (int nt = 0; nt < 8; nt++) {
            mx0 = fmaxf(mx0, fmaxf(s[nt][0], s[nt][1]));
            mx1 = fmaxf(mx1, fmaxf(s[nt][2], s[nt][3]));
        }
        mx0 = fmaxf(mx0, __shfl_xor_sync(0xffffffffu, mx0, 1));
        mx0 = fmaxf(mx0, __shfl_xor_sync(0xffffffffu, mx0, 2));
        mx1 = fmaxf(mx1, __shfl_xor_sync(0xffffffffu, mx1, 1));
        mx1 = fmaxf(mx1, __shfl_xor_sync(0xffffffffu, mx1, 2));
        float mn0 = fmaxf(mrow0, mx0), mn1 = fmaxf(mrow1, mx1);
        float sc0 = __expf(mrow0 - mn0), sc1 = __expf(mrow1 - mn1);
        mrow0 = mn0; mrow1 = mn1;
        float rs0 = 0.f, rs1 = 0.f;
        #pragma unroll
        for (int nt = 0; nt < 8; nt++) {
            s[nt][0] = __expf(s[nt][0] - mn0); rs0 += s[nt][0];
            s[nt][1] = __expf(s[nt][1] - mn0); rs0 += s[nt][1];
            s[nt][2] = __expf(s[nt][2] - mn1); rs1 += s[nt][2];
            s[nt][3] = __expf(s[nt][3] - mn1); rs1 += s[nt][3];
        }
        rs0 += __shfl_xor_sync(0xffffffffu, rs0, 1);
        rs0 += __shfl_xor_sync(0xffffffffu, rs0, 2);
        rs1 += __shfl_xor_sync(0xffffffffu, rs1, 1);
        rs1 += __shfl_xor_sync(0xffffffffu, rs1, 2);
        lrow0 = lrow0*sc0 + rs0; lrow1 = lrow1*sc1 + rs1;
        #pragma unroll
        for (int nt = 0; nt < 8; nt++) {
            o[nt][0] *= sc0; o[nt][1] *= sc0;
            o[nt][2] *= sc1; o[nt][3] *= sc1;
        }
        #pragma unroll
        for (int ks = 0; ks < 4; ks++) {
            uint32_t pah[4], pal[4];
            split2(s[2*ks][0],   s[2*ks][1],   pah[0], pal[0]);
            split2(s[2*ks][2],   s[2*ks][3],   pah[1], pal[1]);
            split2(s[2*ks+1][0], s[2*ks+1][1], pah[2], pal[2]);
            split2(s[2*ks+1][2], s[2*ks+1][3], pah[3], pal[3]);
            uint32_t vh_[8][2], vl_[8][2];
            #pragma unroll
            for (int ntp = 0; ntp < 4; ntp++) {
                uint32_t r0, r1, r2, r3;
                uint32_t addr = sbase + VHo + (uint32_t)(ks*16 + (lane & 15)) * 144u
                              + (uint32_t)(ntp*32) + ((lane >> 4) << 4);
                ldsm_x4_t(r0, r1, r2, r3, addr);
                vh_[2*ntp][0] = r0; vh_[2*ntp][1] = r1;
                vh_[2*ntp+1][0] = r2; vh_[2*ntp+1][1] = r3;
                ldsm_x4_t(r0, r1, r2, r3, addr + (VLo - VHo));
                vl_[2*ntp][0] = r0; vl_[2*ntp][1] = r1;
                vl_[2*ntp+1][0] = r2; vl_[2*ntp+1][1] = r3;
            }
            #pragma unroll
            for (int nt = 0; nt < 8; nt++) {
                mma16816(o[nt], pah, vh_[nt]);
                mma16816(o[nt], pah, vl_[nt]);
                mma16816(o[nt], pal, vh_[nt]);
            }
        }
    }
    float inv0 = 1.f / lrow0, inv1 = 1.f / lrow1;
    #pragma unroll
    for (int nt = 0; nt < 8; nt++) {
        int col = h*64 + nt*8 + tig*2;
        float v0 = o[nt][0]*inv0, v1 = o[nt][1]*inv0;
        float u0 = o[nt][2]*inv1, u1 = o[nt][3]*inv1;
        float x2 = __shfl_down_sync(0xffffffffu, v0, 1);
        float x3 = __shfl_down_sync(0xffffffffu, v1, 1);
        float y2 = __shfl_down_sync(0xffffffffu, u0, 1);
        float y3 = __shfl_down_sync(0xffffffffu, u1, 1);
        if ((tig & 1) == 0) {
            uint2 hi, lo;
            split4(make_float4(v0, v1, x2, x3), hi, lo);
            outs[(size_t)(b*SS + qr0) * 192 + (col >> 2)] = make_uint4(hi.x, hi.y, lo.x, lo.y);
            split4(make_float4(u0, u1, y2, y3), hi, lo);
            outs[(size_t)(b*SS + qr1) * 192 + (col >> 2)] = make_uint4(hi.x, hi.y, lo.x, lo.y);
        }
    }
}

// ---------------- position ids ----------------
__global__ void posids_kernel(const float* __restrict__ amask, int* __restrict__ pos) {
    int b = blockIdx.x;
    if (threadIdx.x == 0) {
        float c = 0.f;
        for (int s = 0; s < SS; s++) {
            float m = amask[b*SS + s];
            c += m;
            pos[b*SS + s] = (m == 0.f) ? 0 : (int)(c - 1.f);
        }
    }
}

// ---------------- embedding ----------------
__global__ void embed_kernel(const int* __restrict__ ids, const int* __restrict__ pos,
                             const float* __restrict__ tok, const float* __restrict__ pemb,
                             float* __restrict__ x) {
    int row = blockIdx.x;
    int id = ids[row];
    int p  = pos[row];
    int tid = threadIdx.x;
    #pragma unroll
    for (int t = 0; t < 3; t++) {
        int d = tid + t*256;
        x[(size_t)row*DD + d] = tok[(size_t)id*DD + d] + pemb[(size_t)p*DD + d];
    }
}

// ---------------- layernorm -> split output (192 threads) ----------------
__global__ void ln_split_kernel(const float* __restrict__ x, const float* __restrict__ g,
                                const float* __restrict__ b, uint4* __restrict__ ys) {
    __shared__ float pr[6];
    int row = blockIdx.x, tid = threadIdx.x;   // 192 threads
    float4 v = ((const float4*)(x + (size_t)row*DD))[tid];
    float s = v.x + v.y + v.z + v.w;
    #pragma unroll
    for (int o = 16; o; o >>= 1) s += __shfl_xor_sync(0xffffffffu, s, o);
    if ((tid & 31) == 0) pr[tid >> 5] = s;
    __syncthreads();
    float mu = (pr[0]+pr[1]+pr[2]+pr[3]+pr[4]+pr[5]) * (1.f/DD);
    float dx = v.x-mu, dy = v.y-mu, dz = v.z-mu, dw = v.w-mu;
    float s2 = dx*dx + dy*dy + dz*dz + dw*dw;
    #pragma unroll
    for (int o = 16; o; o >>= 1) s2 += __shfl_xor_sync(0xffffffffu, s2, o);
    __syncthreads();
    if ((tid & 31) == 0) pr[tid >> 5] = s2;
    __syncthreads();
    float rstd = rsqrtf((pr[0]+pr[1]+pr[2]+pr[3]+pr[4]+pr[5]) * (1.f/DD) + 1e-5f);
    float4 gg = ((const float4*)g)[tid], bb = ((const float4*)b)[tid];
    float4 y = make_float4(dx*rstd*gg.x + bb.x, dy*rstd*gg.y + bb.y,
                           dz*rstd*gg.z + bb.z, dw*rstd*gg.w + bb.w);
    uint2 hi, lo; split4(y, hi, lo);
    ys[(size_t)row*192 + tid] = make_uint4(hi.x, hi.y, lo.x, lo.y);
}

// ---------------- launch ----------------
extern "C" void kernel_launch(void* const* d_in, const int* in_sizes, int n_in,
                              void* d_out, int out_size) {
    const int*   ids   = (const int*)  d_in[0];
    const float* amask = (const float*)d_in[1];
    const float* tok   = (const float*)d_in[2];
    const float* pemb  = (const float*)d_in[3];
    const float* ln1g  = (const float*)d_in[4];
    const float* ln1b  = (const float*)d_in[5];
    const float* Wq    = (const float*)d_in[6];
    const float* bq    = (const float*)d_in[7];
    const float* Wk    = (const float*)d_in[8];
    const float* bk    = (const float*)d_in[9];
    const float* Wv    = (const float*)d_in[10];
    const float* bv    = (const float*)d_in[11];
    const float* Wp    = (const float*)d_in[12];
    const float* bp    = (const float*)d_in[13];
    const float* ln2g  = (const float*)d_in[14];
    const float* ln2b  = (const float*)d_in[15];
    const float* W1    = (const float*)d_in[16];
    const float* b1    = (const float*)d_in[17];
    const float* W2    = (const float*)d_in[18];
    const float* b2    = (const float*)d_in[19];
    const float* lnfg  = (const float*)d_in[20];
    const float* lnfb  = (const float*)d_in[21];
    float* out = (float*)d_out;

    float *xp; int* pidp;
    uint4 *hs, *qkvs, *as, *fs, *wqs, *wks, *wvs, *wps, *w1s, *w2s, *toks;
    cudaGetSymbolAddress((void**)&xp,   g_x);
    cudaGetSymbolAddress((void**)&pidp, g_pos);
    cudaGetSymbolAddress((void**)&hs,   g_h_s);
    cudaGetSymbolAddress((void**)&qkvs, g_qkv_s);
    cudaGetSymbolAddress((void**)&as,   g_attn_s);
    cudaGetSymbolAddress((void**)&fs,   g_ff_s);
    cudaGetSymbolAddress((void**)&wqs,  g_wq_s);
    cudaGetSymbolAddress((void**)&wks,  g_wk_s);
    cudaGetSymbolAddress((void**)&wvs,  g_wv_s);
    cudaGetSymbolAddress((void**)&wps,  g_wp_s);
    cudaGetSymbolAddress((void**)&w1s,  g_w1_s);
    cudaGetSymbolAddress((void**)&w2s,  g_w2_s);
    cudaGetSymbolAddress((void**)&toks, g_tok_s);

    const int SM_T0 = 2*(20480 + 2*8704);   // 75776
    const int SM_T1 = 2*(20480 + 2*10240);  // 81920
    cudaFuncSetAttribute(mma_gemm<0,0>, cudaFuncAttributeMaxDynamicSharedMemorySize, SM_T0);
    cudaFuncSetAttribute(mma_gemm<0,1>, cudaFuncAttributeMaxDynamicSharedMemorySize, SM_T0);
    cudaFuncSetAttribute(mma_gemm<1,0>, cudaFuncAttributeMaxDynamicSharedMemorySize, SM_T1);
    cudaFuncSetAttribute(qkv_gemm, cudaFuncAttributeMaxDynamicSharedMemorySize, SM_T0);

    const int SG = 1184;
    split_kernel<<<SG, 256>>>((const float4*)Wq, wqs, LL*DD*DD/4);
    split_kernel<<<SG, 256>>>((const float4*)Wk, wks, LL*DD*DD/4);
    split_kernel<<<SG, 256>>>((const float4*)Wv, wvs, LL*DD*DD/4);
    split_kernel<<<SG, 256>>>((const float4*)Wp, wps, LL*DD*DD/4);
    split_kernel<<<SG, 256>>>((const float4*)W1, w1s, LL*DD*FF/4);
    split_kernel<<<SG, 256>>>((const float4*)W2, w2s, LL*DD*FF/4);
    split_kernel<<<SG, 256>>>((const float4*)tok, toks, VV*DD/4);

    posids_kernel<<<BB, 32>>>(amask, pidp);
    embed_kernel<<<MM, 256>>>(ids, pidp, tok, pemb, xp);

    dim3 gD(DD/128, MM/128);
    dim3 gQKV(18, MM/128);
    dim3 gF(FF/128, MM/128);
    dim3 gV((VV+127)/128, MM/128);
    dim3 gFA(SS/64, BB*HH);

    for (int l = 0; l < LL; l++) {
        const uint4* wql = wqs + (size_t)l*(DD*DD/4);
        const uint4* wkl = wks + (size_t)l*(DD*DD/4);
        const uint4* wvl = wvs + (size_t)l*(DD*DD/4);
        const uint4* wpl = wps + (size_t)l*(DD*DD/4);
        const uint4* w1l = w1s + (size_t)l*(DD*FF/4);
        const uint4* w2l = w2s + (size_t)l*(DD*FF/4);

        ln_split_kernel<<<MM, 192>>>(xp, ln1g + l*DD, ln1b + l*DD, hs);
        qkv_gemm<<<gQKV, 256, SM_T0>>>(hs, wql, wkl, wvl, bq + l*DD, bk + l*DD, bv + l*DD, qkvs);
        flash_kernel<<<gFA, 128>>>(qkvs, amask, as);
        mma_gemm<0,0><<<gD, 256, SM_T0>>>(as, wpl, bp + l*DD, xp, xp, nullptr, MM, DD, DD, 0);
        ln_split_kernel<<<MM, 192>>>(xp, ln2g + l*DD, ln2b + l*DD, hs);
        mma_gemm<0,1><<<gF, 256, SM_T0>>>(hs, w1l, b1 + l*FF, nullptr, nullptr, fs, MM, FF, DD, 1);
        mma_gemm<0,0><<<gD, 256, SM_T0>>>(fs, w2l, b2 + l*DD, xp, xp, nullptr, MM, DD, FF, 0);
    }

    ln_split_kernel<<<MM, 192>>>(xp, lnfg, lnfb, hs);
    mma_gemm<1,0><<<gV, 256, SM_T1>>>(hs, toks, nullptr, nullptr, out, nullptr, MM, VV, DD, 0);
}